// round 3
// baseline (speedup 1.0000x reference)
#include <cuda_runtime.h>

#define NN 10000
#define EE 160000
#define EPS 1e-5f
#define CEILDIV(a,b) (((a)+(b)-1)/(b))

// ---------------- scratch (static device globals; no allocation) ----------------
__device__ __align__(16) float g_deg[NN];        // degree -> dis (rsqrt) in place
__device__ __align__(16) float g_norm[EE];       // normalized edge weights
__device__ __align__(16) int   g_cnt[NN];        // per-dst edge counts
__device__ __align__(16) int   g_rowptr[NN + 1]; // CSR row pointers (by dst)
__device__ __align__(16) int   g_cursor[NN];     // fill cursors
__device__ __align__(16) int   g_csrc[EE];       // CSR src indices
__device__ __align__(16) float g_cw[EE];         // CSR weights
__device__ __align__(16) float g_y1[NN * 512];   // layer1 out / h1 (in-place BN)
__device__ __align__(16) float g_t1[NN * 512];   // prop(h1)
__device__ __align__(16) float g_y2[NN * 256];   // layer2 out / h2
__device__ __align__(16) float g_p2[NN * 256];   // prop(h2) = Tx1
__device__ __align__(16) float g_tx2[NN * 256];  // 2*prop(Tx1) - h2 = Tx2
__device__ __align__(16) float g_y3[NN * 128];   // layer3 out / h3
__device__ __align__(16) float g_sum[512];
__device__ __align__(16) float g_ssq[512];

// device-side buffer selection (no host-side symbol address queries)
__device__ __forceinline__ float* buf(int id) {
    switch (id) {
        case 1: return g_y1;
        case 2: return g_t1;
        case 3: return g_y2;
        case 4: return g_p2;
        case 5: return g_tx2;
        case 6: return g_y3;
    }
    return nullptr;
}

// ---------------- small utility kernels ----------------
__global__ void k_init_graph() {
    int i = blockIdx.x * blockDim.x + threadIdx.x;
    if (i < NN) { g_deg[i] = 0.0f; g_cnt[i] = 0; }
}

__global__ void k_zero_sums(int F) {
    int i = blockIdx.x * blockDim.x + threadIdx.x;
    if (i < F) { g_sum[i] = 0.0f; g_ssq[i] = 0.0f; }
}

// edge_index is int32 on device (JAX default x64-disabled downcasts int64->int32)
__global__ void k_deg(const int* __restrict__ ei, const float* __restrict__ ea) {
    int e = blockIdx.x * blockDim.x + threadIdx.x;
    if (e >= EE) return;
    atomicAdd(&g_deg[ei[e]], ea[e]);
}

__global__ void k_dis() {
    int i = blockIdx.x * blockDim.x + threadIdx.x;
    if (i >= NN) return;
    float d = g_deg[i];
    g_deg[i] = (d > 0.0f) ? rsqrtf(d) : 0.0f;
}

__global__ void k_norm(const int* __restrict__ ei, const float* __restrict__ ea) {
    int e = blockIdx.x * blockDim.x + threadIdx.x;
    if (e >= EE) return;
    int s = ei[e];
    int d = ei[EE + e];
    g_norm[e] = -g_deg[s] * ea[e] * g_deg[d];
    atomicAdd(&g_cnt[d], 1);
}

// one-block exclusive scan of g_cnt -> g_rowptr, g_cursor
__global__ void k_scan() {
    __shared__ int sh[1024];
    __shared__ int carrySh;
    int tid = threadIdx.x;
    if (tid == 0) carrySh = 0;
    __syncthreads();
    for (int base = 0; base < NN; base += 1024) {
        int i = base + tid;
        int v = (i < NN) ? g_cnt[i] : 0;
        sh[tid] = v;
        __syncthreads();
        for (int off = 1; off < 1024; off <<= 1) {
            int t = (tid >= off) ? sh[tid - off] : 0;
            __syncthreads();
            sh[tid] += t;
            __syncthreads();
        }
        int carry = carrySh;
        int excl = carry + sh[tid] - v;
        if (i < NN) { g_rowptr[i] = excl; g_cursor[i] = excl; }
        int total = sh[1023];
        __syncthreads();
        if (tid == 0) carrySh = carry + total;
        __syncthreads();
    }
    if (tid == 0) g_rowptr[NN] = carrySh;
}

__global__ void k_fill(const int* __restrict__ ei) {
    int e = blockIdx.x * blockDim.x + threadIdx.x;
    if (e >= EE) return;
    int d = ei[EE + e];
    int pos = atomicAdd(&g_cursor[d], 1);
    g_csrc[pos] = ei[e];
    g_cw[pos] = g_norm[e];
}

// ---------------- SGEMM: C[M,N] = A[M,K] @ B[K,N] (+bias | +=) ----------------
// 128x128 block tile, BK=8, 256 threads, 8x8 micro-tile (split 4+4 for LDS.128)
#define BM 128
#define BN 128
#define BK 8
__global__ __launch_bounds__(256) void sgemm(
    const float* __restrict__ Aext, int Aid,
    const float* __restrict__ B,
    const float* __restrict__ bias, int Cid,
    int M, int N, int K, int accum)
{
    const float* A = Aext ? Aext : buf(Aid);
    float* C = buf(Cid);
    __shared__ float As[BK][BM];
    __shared__ float Bs[BK][BN];
    const int tid = threadIdx.x;
    const int row0 = blockIdx.y * BM;
    const int col0 = blockIdx.x * BN;
    const int tx = tid & 15;
    const int ty = tid >> 4;
    const int aRow = tid >> 1;
    const int aCol = (tid & 1) << 2;
    const int bRow = tid >> 5;
    const int bCol = (tid & 31) << 2;

    float acc[8][8];
#pragma unroll
    for (int i = 0; i < 8; i++)
#pragma unroll
        for (int j = 0; j < 8; j++) acc[i][j] = 0.0f;

    const bool aValid = (row0 + aRow) < M;
    const float* Abase = A + (size_t)(row0 + aRow) * K + aCol;
    const float* Bbase = B + (size_t)bRow * N + col0 + bCol;

    for (int k0 = 0; k0 < K; k0 += BK) {
        float4 av = make_float4(0.f, 0.f, 0.f, 0.f);
        if (aValid) av = *(const float4*)(Abase + k0);
        As[aCol + 0][aRow] = av.x;
        As[aCol + 1][aRow] = av.y;
        As[aCol + 2][aRow] = av.z;
        As[aCol + 3][aRow] = av.w;
        float4 bv = *(const float4*)(Bbase + (size_t)k0 * N);
        *(float4*)&Bs[bRow][bCol] = bv;
        __syncthreads();
#pragma unroll
        for (int k = 0; k < BK; k++) {
            float a[8], b[8];
            *(float4*)&a[0] = *(const float4*)&As[k][ty * 4];
            *(float4*)&a[4] = *(const float4*)&As[k][64 + ty * 4];
            *(float4*)&b[0] = *(const float4*)&Bs[k][tx * 4];
            *(float4*)&b[4] = *(const float4*)&Bs[k][64 + tx * 4];
#pragma unroll
            for (int i = 0; i < 8; i++)
#pragma unroll
                for (int j = 0; j < 8; j++)
                    acc[i][j] += a[i] * b[j];
        }
        __syncthreads();
    }

#pragma unroll
    for (int i = 0; i < 8; i++) {
        int r = row0 + ((i < 4) ? (ty * 4 + i) : (64 + ty * 4 + (i - 4)));
        if (r >= M) continue;
        float* Crow = C + (size_t)r * N + col0;
#pragma unroll
        for (int half = 0; half < 2; half++) {
            int c = (half == 0) ? (tx * 4) : (64 + tx * 4);
            float4 v;
            v.x = acc[i][half * 4 + 0];
            v.y = acc[i][half * 4 + 1];
            v.z = acc[i][half * 4 + 2];
            v.w = acc[i][half * 4 + 3];
            if (accum) {
                float4 old = *(float4*)(Crow + c);
                v.x += old.x; v.y += old.y; v.z += old.z; v.w += old.w;
            } else if (bias) {
                v.x += bias[col0 + c + 0];
                v.y += bias[col0 + c + 1];
                v.z += bias[col0 + c + 2];
                v.w += bias[col0 + c + 3];
            }
            *(float4*)(Crow + c) = v;
        }
    }
}

// ---------------- BN (training mode over node dim) ----------------
// grid: (F/32, 32), block: 256 = 8 rows x 32 cols
__global__ void k_bn_stats(int xid, int n, int F) {
    const float* x = buf(xid);
    int lane = threadIdx.x & 31;
    int ty = threadIdx.x >> 5;
    int col = blockIdx.x * 32 + lane;
    float s = 0.0f, q = 0.0f;
    for (int r = blockIdx.y * 8 + ty; r < n; r += gridDim.y * 8) {
        float v = x[(size_t)r * F + col];
        s += v;
        q += v * v;
    }
    __shared__ float shS[8][33];
    __shared__ float shQ[8][33];
    shS[ty][lane] = s;
    shQ[ty][lane] = q;
    __syncthreads();
    if (ty == 0) {
#pragma unroll
        for (int i = 1; i < 8; i++) { s += shS[i][lane]; q += shQ[i][lane]; }
        atomicAdd(&g_sum[col], s);
        atomicAdd(&g_ssq[col], q);
    }
}

__global__ void k_bn_apply(int xid, const float* __restrict__ gamma,
                           const float* __restrict__ beta, int n, int F, int relu) {
    float* x = buf(xid);
    int idx = blockIdx.x * blockDim.x + threadIdx.x;
    if (idx >= n * F) return;
    int f = idx % F;
    float inv_n = 1.0f / (float)n;
    float mu = g_sum[f] * inv_n;
    float var = g_ssq[f] * inv_n - mu * mu;
    float v = (x[idx] - mu) * rsqrtf(var + EPS) * gamma[f] + beta[f];
    if (relu) v = fmaxf(v, 0.0f);
    x[idx] = v;
}

// ---------------- propagation: out[d] = sum_e norm_e * h[src_e]  (CSR by dst) ----------------
// block per node, blockDim = F/4, float4 per thread
__global__ void k_prop(int hid, int outid, int F) {
    const float* h = buf(hid);
    float* out = buf(outid);
    int node = blockIdx.x;
    int t = threadIdx.x;
    int beg = g_rowptr[node];
    int end = g_rowptr[node + 1];
    float4 acc = make_float4(0.f, 0.f, 0.f, 0.f);
    for (int e = beg; e < end; e++) {
        int s = g_csrc[e];
        float w = g_cw[e];
        float4 v = *(const float4*)(h + (size_t)s * F + t * 4);
        acc.x += w * v.x; acc.y += w * v.y; acc.z += w * v.z; acc.w += w * v.w;
    }
    *(float4*)(out + (size_t)node * F + t * 4) = acc;
}

// Cheb step: out[d] = 2 * prop(h)[d] - sub[d]
__global__ void k_prop_cheb(int hid, int subid, int outid, int F) {
    const float* h = buf(hid);
    const float* sub = buf(subid);
    float* out = buf(outid);
    int node = blockIdx.x;
    int t = threadIdx.x;
    int beg = g_rowptr[node];
    int end = g_rowptr[node + 1];
    float4 acc = make_float4(0.f, 0.f, 0.f, 0.f);
    for (int e = beg; e < end; e++) {
        int s = g_csrc[e];
        float w = g_cw[e];
        float4 v = *(const float4*)(h + (size_t)s * F + t * 4);
        acc.x += w * v.x; acc.y += w * v.y; acc.z += w * v.z; acc.w += w * v.w;
    }
    float4 sv = *(const float4*)(sub + (size_t)node * F + t * 4);
    float4 r;
    r.x = 2.0f * acc.x - sv.x;
    r.y = 2.0f * acc.y - sv.y;
    r.z = 2.0f * acc.z - sv.z;
    r.w = 2.0f * acc.w - sv.w;
    *(float4*)(out + (size_t)node * F + t * 4) = r;
}

// ---------------- fc (128 -> 6) + log_softmax, warp per node ----------------
__global__ void k_fc(const float* __restrict__ W,
                     const float* __restrict__ bias, float* __restrict__ out, int n) {
    const float* h = g_y3;
    int gtid = blockIdx.x * blockDim.x + threadIdx.x;
    int node = gtid >> 5;
    int lane = gtid & 31;
    if (node >= n) return;
    float hv[4];
#pragma unroll
    for (int k = 0; k < 4; k++) hv[k] = h[(size_t)node * 128 + lane + 32 * k];
    float logit[6];
#pragma unroll
    for (int j = 0; j < 6; j++) {
        float s = 0.0f;
#pragma unroll
        for (int k = 0; k < 4; k++) s += hv[k] * W[(lane + 32 * k) * 6 + j];
#pragma unroll
        for (int o = 16; o > 0; o >>= 1) s += __shfl_xor_sync(0xffffffff, s, o);
        logit[j] = s + bias[j];
    }
    if (lane == 0) {
        float mx = logit[0];
#pragma unroll
        for (int j = 1; j < 6; j++) mx = fmaxf(mx, logit[j]);
        float se = 0.0f;
#pragma unroll
        for (int j = 0; j < 6; j++) se += expf(logit[j] - mx);
        float lse = mx + logf(se);
#pragma unroll
        for (int j = 0; j < 6; j++) out[(size_t)node * 6 + j] = logit[j] - lse;
    }
}

// ---------------- launch ----------------
extern "C" void kernel_launch(void* const* d_in, const int* in_sizes, int n_in,
                              void* d_out, int out_size) {
    const float* x    = (const float*)d_in[0];
    const int*   ei   = (const int*)d_in[1];
    const float* ea   = (const float*)d_in[2];
    const float* W1_0 = (const float*)d_in[3];
    const float* b1   = (const float*)d_in[4];
    const float* g1   = (const float*)d_in[5];
    const float* be1  = (const float*)d_in[6];
    const float* W2_0 = (const float*)d_in[7];
    const float* W2_1 = (const float*)d_in[8];
    const float* b2   = (const float*)d_in[9];
    const float* g2   = (const float*)d_in[10];
    const float* be2  = (const float*)d_in[11];
    const float* W3_0 = (const float*)d_in[12];
    const float* W3_1 = (const float*)d_in[13];
    const float* W3_2 = (const float*)d_in[14];
    const float* b3   = (const float*)d_in[15];
    const float* g3   = (const float*)d_in[16];
    const float* be3  = (const float*)d_in[17];
    const float* fcW  = (const float*)d_in[18];
    const float* fcb  = (const float*)d_in[19];
    float* out = (float*)d_out;

    // ---- graph normalization + CSR build ----
    k_init_graph<<<CEILDIV(NN, 256), 256>>>();
    k_deg<<<CEILDIV(EE, 256), 256>>>(ei, ea);
    k_dis<<<CEILDIV(NN, 256), 256>>>();
    k_norm<<<CEILDIV(EE, 256), 256>>>(ei, ea);
    k_scan<<<1, 1024>>>();
    k_fill<<<CEILDIV(EE, 256), 256>>>(ei);

    // ---- layer 1: K=1 cheb = x @ W1_0 + b1 ; BN ; relu ----
    {
        dim3 grid(512 / BN, CEILDIV(NN, BM));
        sgemm<<<grid, 256>>>(x, 0, W1_0, b1, 1, NN, 512, 768, 0);
    }
    k_zero_sums<<<2, 256>>>(512);
    k_bn_stats<<<dim3(512 / 32, 32), 256>>>(1, NN, 512);
    k_bn_apply<<<CEILDIV(NN * 512, 256), 256>>>(1, g1, be1, NN, 512, 1);

    // ---- layer 2: K=2 ----
    k_prop<<<NN, 128>>>(1, 2, 512);
    {
        dim3 grid(256 / BN, CEILDIV(NN, BM));
        sgemm<<<grid, 256>>>(nullptr, 1, W2_0, b2, 3, NN, 256, 512, 0);
        sgemm<<<grid, 256>>>(nullptr, 2, W2_1, nullptr, 3, NN, 256, 512, 1);
    }
    k_zero_sums<<<1, 256>>>(256);
    k_bn_stats<<<dim3(256 / 32, 32), 256>>>(3, NN, 256);
    k_bn_apply<<<CEILDIV(NN * 256, 256), 256>>>(3, g2, be2, NN, 256, 1);

    // ---- layer 3: K=3 ----
    k_prop<<<NN, 64>>>(3, 4, 256);
    k_prop_cheb<<<NN, 64>>>(4, 3, 5, 256);
    {
        dim3 grid(128 / BN, CEILDIV(NN, BM));
        sgemm<<<grid, 256>>>(nullptr, 3, W3_0, b3,      6, NN, 128, 256, 0);
        sgemm<<<grid, 256>>>(nullptr, 4, W3_1, nullptr, 6, NN, 128, 256, 1);
        sgemm<<<grid, 256>>>(nullptr, 5, W3_2, nullptr, 6, NN, 128, 256, 1);
    }
    k_zero_sums<<<1, 128>>>(128);
    k_bn_stats<<<dim3(128 / 32, 32), 256>>>(6, NN, 128);
    k_bn_apply<<<CEILDIV(NN * 128, 256), 256>>>(6, g3, be3, NN, 128, 0);

    // ---- fc + log_softmax ----
    k_fc<<<CEILDIV(NN * 32, 256), 256>>>(fcW, fcb, out, NN);
}

// round 4
// speedup vs baseline: 1.4791x; 1.4791x over previous
#include <cuda_runtime.h>

#define NN 10000
#define EE 160000
#define EPS 1e-5f
#define CEILDIV(a,b) (((a)+(b)-1)/(b))

// ---------------- scratch (static device globals; no allocation) ----------------
__device__ __align__(16) float g_deg[NN];
__device__ __align__(16) float g_norm[EE];
__device__ __align__(16) int   g_cnt[NN];
__device__ __align__(16) int   g_rowptr[NN + 1];
__device__ __align__(16) int   g_cursor[NN];
__device__ __align__(16) int   g_csrc[EE];
__device__ __align__(16) float g_cw[EE];
__device__ __align__(16) float g_y1[NN * 512];   // h1
__device__ __align__(16) float g_t1[NN * 512];   // prop(h1)
__device__ __align__(16) float g_y2[NN * 256];   // h2
__device__ __align__(16) float g_p2[NN * 256];   // Tx1
__device__ __align__(16) float g_tx2[NN * 256];  // Tx2
__device__ __align__(16) float g_y3[NN * 128];   // h3
__device__ __align__(16) float g_sum[512];
__device__ __align__(16) float g_ssq[512];

__device__ __forceinline__ float* buf(int id) {
    switch (id) {
        case 1: return g_y1;
        case 2: return g_t1;
        case 3: return g_y2;
        case 4: return g_p2;
        case 5: return g_tx2;
        case 6: return g_y3;
    }
    return nullptr;
}

// ---------------- graph build ----------------
__global__ void k_init_graph() {
    int i = blockIdx.x * blockDim.x + threadIdx.x;
    if (i < NN) { g_deg[i] = 0.0f; g_cnt[i] = 0; }
}
__global__ void k_zero_sums(int F) {
    int i = blockIdx.x * blockDim.x + threadIdx.x;
    if (i < F) { g_sum[i] = 0.0f; g_ssq[i] = 0.0f; }
}
__global__ void k_deg(const int* __restrict__ ei, const float* __restrict__ ea) {
    int e = blockIdx.x * blockDim.x + threadIdx.x;
    if (e >= EE) return;
    atomicAdd(&g_deg[ei[e]], ea[e]);
}
__global__ void k_dis() {
    int i = blockIdx.x * blockDim.x + threadIdx.x;
    if (i >= NN) return;
    float d = g_deg[i];
    g_deg[i] = (d > 0.0f) ? rsqrtf(d) : 0.0f;
}
__global__ void k_norm(const int* __restrict__ ei, const float* __restrict__ ea) {
    int e = blockIdx.x * blockDim.x + threadIdx.x;
    if (e >= EE) return;
    int s = ei[e];
    int d = ei[EE + e];
    g_norm[e] = -g_deg[s] * ea[e] * g_deg[d];
    atomicAdd(&g_cnt[d], 1);
}
__global__ void k_scan() {
    __shared__ int sh[1024];
    __shared__ int carrySh;
    int tid = threadIdx.x;
    if (tid == 0) carrySh = 0;
    __syncthreads();
    for (int base = 0; base < NN; base += 1024) {
        int i = base + tid;
        int v = (i < NN) ? g_cnt[i] : 0;
        sh[tid] = v;
        __syncthreads();
        for (int off = 1; off < 1024; off <<= 1) {
            int t = (tid >= off) ? sh[tid - off] : 0;
            __syncthreads();
            sh[tid] += t;
            __syncthreads();
        }
        int carry = carrySh;
        int excl = carry + sh[tid] - v;
        if (i < NN) { g_rowptr[i] = excl; g_cursor[i] = excl; }
        int total = sh[1023];
        __syncthreads();
        if (tid == 0) carrySh = carry + total;
        __syncthreads();
    }
    if (tid == 0) g_rowptr[NN] = carrySh;
}
__global__ void k_fill(const int* __restrict__ ei) {
    int e = blockIdx.x * blockDim.x + threadIdx.x;
    if (e >= EE) return;
    int d = ei[EE + e];
    int pos = atomicAdd(&g_cursor[d], 1);
    g_csrc[pos] = ei[e];
    g_cw[pos] = g_norm[e];
}

// ---------------- tf32 tensor-core GEMM ----------------
// C[M,N] = concat_K(A_segs) @ concat_K(B_segs) + bias
// 128x128 CTA tile, BK=16, 256 threads = 8 warps of 64x32, mma m16n8k8 tf32.
#define BM 128
#define BN 128
#define BKT 16
#define SPAD 136   // smem row pitch (floats): mult of 4 (float4 STS) and conflict-free frags

__device__ __forceinline__ unsigned f2tf(float x) {
    unsigned u;
    asm("cvt.rna.tf32.f32 %0, %1;" : "=r"(u) : "f"(x));
    return u;
}

__global__ __launch_bounds__(256) void gemm_tf32(
    const float* __restrict__ Aext, int aid0, int aid1, int aid2,
    const float* __restrict__ B0, const float* __restrict__ B1, const float* __restrict__ B2,
    const float* __restrict__ bias, int Cid,
    int M, int N, int Kseg, int segs)
{
    __shared__ float As[BKT][SPAD];   // [k][m]
    __shared__ float Bs[BKT][SPAD];   // [k][n]

    const float* Ap[3];
    Ap[0] = Aext ? Aext : buf(aid0);
    Ap[1] = buf(aid1);
    Ap[2] = buf(aid2);
    const float* Bp[3] = {B0, B1, B2};
    float* C = buf(Cid);

    const int tid = threadIdx.x;
    const int lane = tid & 31;
    const int warp = tid >> 5;
    const int qr = lane >> 2;   // 0..7
    const int qc = lane & 3;    // 0..3
    const int wm = (warp & 1) * 64;   // warp m-offset within CTA tile
    const int wn = (warp >> 1) * 32;  // warp n-offset

    const int row0 = blockIdx.y * BM;
    const int col0 = blockIdx.x * BN;

    // A load mapping: row = tid/2, k-range = (tid&1)*8 .. +8 (two float4, 32B/thread)
    const int arow = tid >> 1;
    const int ak = (tid & 1) << 3;
    const bool avalid = (row0 + arow) < M;

    float acc[4][4][4];
#pragma unroll
    for (int i = 0; i < 4; i++)
#pragma unroll
        for (int j = 0; j < 4; j++)
#pragma unroll
            for (int e = 0; e < 4; e++) acc[i][j][e] = 0.0f;

    const int K = Kseg * segs;
    for (int k0 = 0; k0 < K; k0 += BKT) {
        const int seg = k0 / Kseg;           // uniform: BKT divides Kseg
        const int kloc = k0 - seg * Kseg;
        const float* A = Ap[seg];
        const float* B = Bp[seg];

        // ---- load A tile (128 x 16) ----
        {
            const float* Arow = A + (size_t)(row0 + arow) * Kseg + kloc + ak;
#pragma unroll
            for (int it = 0; it < 2; it++) {
                float4 v = make_float4(0.f, 0.f, 0.f, 0.f);
                if (avalid) v = *(const float4*)(Arow + it * 4);
                int kb = ak + it * 4;
                As[kb + 0][arow] = __uint_as_float(f2tf(v.x));
                As[kb + 1][arow] = __uint_as_float(f2tf(v.y));
                As[kb + 2][arow] = __uint_as_float(f2tf(v.z));
                As[kb + 3][arow] = __uint_as_float(f2tf(v.w));
            }
        }
        // ---- load B tile (16 x 128) ----
        {
#pragma unroll
            for (int it = 0; it < 2; it++) {
                int idx = tid + it * 256;
                int brow = idx >> 5;
                int bcol = (idx & 31) << 2;
                float4 v = *(const float4*)(B + (size_t)(kloc + brow) * N + col0 + bcol);
                float4 w;
                w.x = __uint_as_float(f2tf(v.x));
                w.y = __uint_as_float(f2tf(v.y));
                w.z = __uint_as_float(f2tf(v.z));
                w.w = __uint_as_float(f2tf(v.w));
                *(float4*)&Bs[brow][bcol] = w;
            }
        }
        __syncthreads();

        // ---- compute: 2 k-steps of 8, 4x4 m16n8 subtiles per warp ----
#pragma unroll
        for (int kk = 0; kk < BKT; kk += 8) {
            unsigned af[4][4], bf[4][2];
#pragma unroll
            for (int i = 0; i < 4; i++) {
                int m0 = wm + 16 * i + qr;
                af[i][0] = __float_as_uint(As[kk + qc][m0]);
                af[i][1] = __float_as_uint(As[kk + qc][m0 + 8]);
                af[i][2] = __float_as_uint(As[kk + qc + 4][m0]);
                af[i][3] = __float_as_uint(As[kk + qc + 4][m0 + 8]);
            }
#pragma unroll
            for (int j = 0; j < 4; j++) {
                int n0 = wn + 8 * j + qr;
                bf[j][0] = __float_as_uint(Bs[kk + qc][n0]);
                bf[j][1] = __float_as_uint(Bs[kk + qc + 4][n0]);
            }
#pragma unroll
            for (int i = 0; i < 4; i++)
#pragma unroll
                for (int j = 0; j < 4; j++) {
                    asm volatile(
                        "mma.sync.aligned.m16n8k8.row.col.f32.tf32.tf32.f32 "
                        "{%0,%1,%2,%3}, {%4,%5,%6,%7}, {%8,%9}, {%0,%1,%2,%3};"
                        : "+f"(acc[i][j][0]), "+f"(acc[i][j][1]),
                          "+f"(acc[i][j][2]), "+f"(acc[i][j][3])
                        : "r"(af[i][0]), "r"(af[i][1]), "r"(af[i][2]), "r"(af[i][3]),
                          "r"(bf[j][0]), "r"(bf[j][1]));
                }
        }
        __syncthreads();
    }

    // ---- epilogue: bias add, bounds-checked float2 stores ----
#pragma unroll
    for (int i = 0; i < 4; i++) {
        int r = row0 + wm + 16 * i + qr;
#pragma unroll
        for (int j = 0; j < 4; j++) {
            int c = col0 + wn + 8 * j + 2 * qc;
            float bx = bias[c], by = bias[c + 1];
            if (r < M) {
                float2 v = make_float2(acc[i][j][0] + bx, acc[i][j][1] + by);
                *(float2*)(C + (size_t)r * N + c) = v;
            }
            if (r + 8 < M) {
                float2 v = make_float2(acc[i][j][2] + bx, acc[i][j][3] + by);
                *(float2*)(C + (size_t)(r + 8) * N + c) = v;
            }
        }
    }
}

// ---------------- BN (training mode over node dim) ----------------
__global__ void k_bn_stats(int xid, int n, int F) {
    const float* x = buf(xid);
    int lane = threadIdx.x & 31;
    int ty = threadIdx.x >> 5;
    int col = blockIdx.x * 32 + lane;
    float s = 0.0f, q = 0.0f;
    for (int r = blockIdx.y * 8 + ty; r < n; r += gridDim.y * 8) {
        float v = x[(size_t)r * F + col];
        s += v;
        q += v * v;
    }
    __shared__ float shS[8][33];
    __shared__ float shQ[8][33];
    shS[ty][lane] = s;
    shQ[ty][lane] = q;
    __syncthreads();
    if (ty == 0) {
#pragma unroll
        for (int i = 1; i < 8; i++) { s += shS[i][lane]; q += shQ[i][lane]; }
        atomicAdd(&g_sum[col], s);
        atomicAdd(&g_ssq[col], q);
    }
}

__global__ void k_bn_apply(int xid, const float* __restrict__ gamma,
                           const float* __restrict__ beta, int n, int F, int relu) {
    float* x = buf(xid);
    int idx = blockIdx.x * blockDim.x + threadIdx.x;
    if (idx >= n * F) return;
    int f = idx % F;
    float inv_n = 1.0f / (float)n;
    float mu = g_sum[f] * inv_n;
    float var = g_ssq[f] * inv_n - mu * mu;
    float v = (x[idx] - mu) * rsqrtf(var + EPS) * gamma[f] + beta[f];
    if (relu) v = fmaxf(v, 0.0f);
    x[idx] = v;
}

// ---------------- propagation (CSR by dst, atomic-free) ----------------
__global__ void k_prop(int hid, int outid, int F) {
    const float* h = buf(hid);
    float* out = buf(outid);
    int node = blockIdx.x;
    int t = threadIdx.x;
    int beg = g_rowptr[node];
    int end = g_rowptr[node + 1];
    float4 acc = make_float4(0.f, 0.f, 0.f, 0.f);
    for (int e = beg; e < end; e++) {
        int s = g_csrc[e];
        float w = g_cw[e];
        float4 v = *(const float4*)(h + (size_t)s * F + t * 4);
        acc.x += w * v.x; acc.y += w * v.y; acc.z += w * v.z; acc.w += w * v.w;
    }
    *(float4*)(out + (size_t)node * F + t * 4) = acc;
}

__global__ void k_prop_cheb(int hid, int subid, int outid, int F) {
    const float* h = buf(hid);
    const float* sub = buf(subid);
    float* out = buf(outid);
    int node = blockIdx.x;
    int t = threadIdx.x;
    int beg = g_rowptr[node];
    int end = g_rowptr[node + 1];
    float4 acc = make_float4(0.f, 0.f, 0.f, 0.f);
    for (int e = beg; e < end; e++) {
        int s = g_csrc[e];
        float w = g_cw[e];
        float4 v = *(const float4*)(h + (size_t)s * F + t * 4);
        acc.x += w * v.x; acc.y += w * v.y; acc.z += w * v.z; acc.w += w * v.w;
    }
    float4 sv = *(const float4*)(sub + (size_t)node * F + t * 4);
    float4 r;
    r.x = 2.0f * acc.x - sv.x;
    r.y = 2.0f * acc.y - sv.y;
    r.z = 2.0f * acc.z - sv.z;
    r.w = 2.0f * acc.w - sv.w;
    *(float4*)(out + (size_t)node * F + t * 4) = r;
}

// ---------------- fc (128 -> 6) + log_softmax ----------------
__global__ void k_fc(const float* __restrict__ W,
                     const float* __restrict__ bias, float* __restrict__ out, int n) {
    const float* h = g_y3;
    int gtid = blockIdx.x * blockDim.x + threadIdx.x;
    int node = gtid >> 5;
    int lane = gtid & 31;
    if (node >= n) return;
    float hv[4];
#pragma unroll
    for (int k = 0; k < 4; k++) hv[k] = h[(size_t)node * 128 + lane + 32 * k];
    float logit[6];
#pragma unroll
    for (int j = 0; j < 6; j++) {
        float s = 0.0f;
#pragma unroll
        for (int k = 0; k < 4; k++) s += hv[k] * W[(lane + 32 * k) * 6 + j];
#pragma unroll
        for (int o = 16; o > 0; o >>= 1) s += __shfl_xor_sync(0xffffffff, s, o);
        logit[j] = s + bias[j];
    }
    if (lane == 0) {
        float mx = logit[0];
#pragma unroll
        for (int j = 1; j < 6; j++) mx = fmaxf(mx, logit[j]);
        float se = 0.0f;
#pragma unroll
        for (int j = 0; j < 6; j++) se += expf(logit[j] - mx);
        float lse = mx + logf(se);
#pragma unroll
        for (int j = 0; j < 6; j++) out[(size_t)node * 6 + j] = logit[j] - lse;
    }
}

// ---------------- launch ----------------
extern "C" void kernel_launch(void* const* d_in, const int* in_sizes, int n_in,
                              void* d_out, int out_size) {
    const float* x    = (const float*)d_in[0];
    const int*   ei   = (const int*)d_in[1];
    const float* ea   = (const float*)d_in[2];
    const float* W1_0 = (const float*)d_in[3];
    const float* b1   = (const float*)d_in[4];
    const float* g1   = (const float*)d_in[5];
    const float* be1  = (const float*)d_in[6];
    const float* W2_0 = (const float*)d_in[7];
    const float* W2_1 = (const float*)d_in[8];
    const float* b2   = (const float*)d_in[9];
    const float* g2   = (const float*)d_in[10];
    const float* be2  = (const float*)d_in[11];
    const float* W3_0 = (const float*)d_in[12];
    const float* W3_1 = (const float*)d_in[13];
    const float* W3_2 = (const float*)d_in[14];
    const float* b3   = (const float*)d_in[15];
    const float* g3   = (const float*)d_in[16];
    const float* be3  = (const float*)d_in[17];
    const float* fcW  = (const float*)d_in[18];
    const float* fcb  = (const float*)d_in[19];
    float* out = (float*)d_out;

    // ---- graph normalization + CSR build ----
    k_init_graph<<<CEILDIV(NN, 256), 256>>>();
    k_deg<<<CEILDIV(EE, 256), 256>>>(ei, ea);
    k_dis<<<CEILDIV(NN, 256), 256>>>();
    k_norm<<<CEILDIV(EE, 256), 256>>>(ei, ea);
    k_scan<<<1, 1024>>>();
    k_fill<<<CEILDIV(EE, 256), 256>>>(ei);

    // ---- layer 1: y1 = x @ W1_0 + b1 ; BN ; relu ----
    gemm_tf32<<<dim3(512 / BN, CEILDIV(NN, BM)), 256>>>(
        x, 0, 0, 0, W1_0, nullptr, nullptr, b1, 1, NN, 512, 768, 1);
    k_zero_sums<<<2, 256>>>(512);
    k_bn_stats<<<dim3(512 / 32, 32), 256>>>(1, NN, 512);
    k_bn_apply<<<CEILDIV(NN * 512, 256), 256>>>(1, g1, be1, NN, 512, 1);

    // ---- layer 2: y2 = [h1 | prop(h1)] @ [W2_0 ; W2_1] + b2 (K=1024) ----
    k_prop<<<NN, 128>>>(1, 2, 512);
    gemm_tf32<<<dim3(256 / BN, CEILDIV(NN, BM)), 256>>>(
        nullptr, 1, 2, 0, W2_0, W2_1, nullptr, b2, 3, NN, 256, 512, 2);
    k_zero_sums<<<1, 256>>>(256);
    k_bn_stats<<<dim3(256 / 32, 32), 256>>>(3, NN, 256);
    k_bn_apply<<<CEILDIV(NN * 256, 256), 256>>>(3, g2, be2, NN, 256, 1);

    // ---- layer 3: y3 = [h2 | Tx1 | Tx2] @ [W3_0;W3_1;W3_2] + b3 (K=768) ----
    k_prop<<<NN, 64>>>(3, 4, 256);
    k_prop_cheb<<<NN, 64>>>(4, 3, 5, 256);
    gemm_tf32<<<dim3(128 / BN, CEILDIV(NN, BM)), 256>>>(
        nullptr, 3, 4, 5, W3_0, W3_1, W3_2, b3, 6, NN, 128, 256, 3);
    k_zero_sums<<<1, 128>>>(128);
    k_bn_stats<<<dim3(128 / 32, 32), 256>>>(6, NN, 128);
    k_bn_apply<<<CEILDIV(NN * 128, 256), 256>>>(6, g3, be3, NN, 128, 0);

    // ---- fc + log_softmax ----
    k_fc<<<CEILDIV(NN * 32, 256), 256>>>(fcW, fcb, out, NN);
}

// round 5
// speedup vs baseline: 2.0836x; 1.4086x over previous
#include <cuda_runtime.h>

#define NN 10000
#define EE 160000
#define EPS 1e-5f
#define CEILDIV(a,b) (((a)+(b)-1)/(b))

// ---------------- scratch (static device globals; no allocation) ----------------
__device__ __align__(16) float g_deg[NN];
__device__ __align__(16) float g_norm[EE];
__device__ __align__(16) int   g_cnt[NN];
__device__ __align__(16) int   g_rowptr[NN + 1];
__device__ __align__(16) int   g_cursor[NN];
__device__ __align__(16) int   g_csrc[EE];
__device__ __align__(16) float g_cw[EE];
__device__ __align__(16) float g_y1[NN * 512];   // h1
__device__ __align__(16) float g_t1[NN * 512];   // prop(h1)
__device__ __align__(16) float g_y2[NN * 256];   // h2
__device__ __align__(16) float g_p2[NN * 256];   // Tx1
__device__ __align__(16) float g_tx2[NN * 256];  // Tx2
__device__ __align__(16) float g_y3[NN * 128];   // h3
__device__ __align__(16) float g_sums[896];      // layer1 @0, layer2 @512, layer3 @768
__device__ __align__(16) float g_ssqs[896];

__device__ __forceinline__ float* buf(int id) {
    switch (id) {
        case 1: return g_y1;
        case 2: return g_t1;
        case 3: return g_y2;
        case 4: return g_p2;
        case 5: return g_tx2;
        case 6: return g_y3;
    }
    return nullptr;
}

// ---------------- graph build ----------------
__global__ void k_init_graph() {
    int i = blockIdx.x * blockDim.x + threadIdx.x;
    if (i < NN) { g_deg[i] = 0.0f; g_cnt[i] = 0; }
    if (i < 896) { g_sums[i] = 0.0f; g_ssqs[i] = 0.0f; }
}
__global__ void k_deg(const int* __restrict__ ei, const float* __restrict__ ea) {
    int e = blockIdx.x * blockDim.x + threadIdx.x;
    if (e >= EE) return;
    atomicAdd(&g_deg[ei[e]], ea[e]);
}
__global__ void k_dis() {
    int i = blockIdx.x * blockDim.x + threadIdx.x;
    if (i >= NN) return;
    float d = g_deg[i];
    g_deg[i] = (d > 0.0f) ? rsqrtf(d) : 0.0f;
}
__global__ void k_norm(const int* __restrict__ ei, const float* __restrict__ ea) {
    int e = blockIdx.x * blockDim.x + threadIdx.x;
    if (e >= EE) return;
    int s = ei[e];
    int d = ei[EE + e];
    g_norm[e] = -g_deg[s] * ea[e] * g_deg[d];
    atomicAdd(&g_cnt[d], 1);
}
__global__ void k_scan() {
    __shared__ int sh[1024];
    __shared__ int carrySh;
    int tid = threadIdx.x;
    if (tid == 0) carrySh = 0;
    __syncthreads();
    for (int base = 0; base < NN; base += 1024) {
        int i = base + tid;
        int v = (i < NN) ? g_cnt[i] : 0;
        sh[tid] = v;
        __syncthreads();
        for (int off = 1; off < 1024; off <<= 1) {
            int t = (tid >= off) ? sh[tid - off] : 0;
            __syncthreads();
            sh[tid] += t;
            __syncthreads();
        }
        int carry = carrySh;
        int excl = carry + sh[tid] - v;
        if (i < NN) { g_rowptr[i] = excl; g_cursor[i] = excl; }
        int total = sh[1023];
        __syncthreads();
        if (tid == 0) carrySh = carry + total;
        __syncthreads();
    }
    if (tid == 0) g_rowptr[NN] = carrySh;
}
__global__ void k_fill(const int* __restrict__ ei) {
    int e = blockIdx.x * blockDim.x + threadIdx.x;
    if (e >= EE) return;
    int d = ei[EE + e];
    int pos = atomicAdd(&g_cursor[d], 1);
    g_csrc[pos] = ei[e];
    g_cw[pos] = g_norm[e];
}

// ---------------- tf32 tensor-core GEMM, software-pipelined, fused BN stats ----------------
// C[M,N] = concat_K(A_segs) @ concat_K(B_segs) + bias; also atomically accumulates
// per-column sum / sum-of-squares into g_sums/g_ssqs at offset soff.
#define BM 128
#define BN 128
#define BKT 16
#define SPAD 136

__device__ __forceinline__ unsigned f2tf(float x) {
    unsigned u;
    asm("cvt.rna.tf32.f32 %0, %1;" : "=r"(u) : "f"(x));
    return u;
}

__global__ __launch_bounds__(256) void gemm_tf32(
    const float* __restrict__ Aext, int aid0, int aid1, int aid2,
    const float* __restrict__ B0, const float* __restrict__ B1, const float* __restrict__ B2,
    const float* __restrict__ bias, int Cid,
    int M, int N, int Kseg, int segs, int soff)
{
    __shared__ float As[2][BKT][SPAD];
    __shared__ float Bs[2][BKT][SPAD];

    const float* Ap[3];
    Ap[0] = Aext ? Aext : buf(aid0);
    Ap[1] = buf(aid1);
    Ap[2] = buf(aid2);
    const float* Bp[3] = {B0, B1, B2};
    float* C = buf(Cid);

    const int tid = threadIdx.x;
    const int lane = tid & 31;
    const int warp = tid >> 5;
    const int qr = lane >> 2;
    const int qc = lane & 3;
    const int wm = (warp & 1) * 64;
    const int wn = (warp >> 1) * 32;

    const int row0 = blockIdx.y * BM;
    const int col0 = blockIdx.x * BN;

    const int arow = tid >> 1;
    const int ak = (tid & 1) << 3;
    const bool avalid = (row0 + arow) < M;
    const int brow = tid >> 5;       // 0..7 (+8 on second half)
    const int bcol = (tid & 31) << 2;

    float acc[4][4][4];
#pragma unroll
    for (int i = 0; i < 4; i++)
#pragma unroll
        for (int j = 0; j < 4; j++)
#pragma unroll
            for (int e = 0; e < 4; e++) acc[i][j][e] = 0.0f;

    const int K = Kseg * segs;

    // ---- tile fetch into registers ----
    float4 rA[2], rB[2];
    auto fetch = [&](int k0) {
        const int seg = k0 / Kseg;
        const int kloc = k0 - seg * Kseg;
        const float* A = Ap[seg];
        const float* B = Bp[seg];
        const float* Arow = A + (size_t)(row0 + arow) * Kseg + kloc + ak;
#pragma unroll
        for (int it = 0; it < 2; it++) {
            rA[it] = make_float4(0.f, 0.f, 0.f, 0.f);
            if (avalid) rA[it] = *(const float4*)(Arow + it * 4);
        }
#pragma unroll
        for (int it = 0; it < 2; it++) {
            rB[it] = *(const float4*)(B + (size_t)(kloc + brow + it * 8) * N + col0 + bcol);
        }
    };
    auto commit = [&](int s) {
#pragma unroll
        for (int it = 0; it < 2; it++) {
            int kb = ak + it * 4;
            As[s][kb + 0][arow] = __uint_as_float(f2tf(rA[it].x));
            As[s][kb + 1][arow] = __uint_as_float(f2tf(rA[it].y));
            As[s][kb + 2][arow] = __uint_as_float(f2tf(rA[it].z));
            As[s][kb + 3][arow] = __uint_as_float(f2tf(rA[it].w));
        }
#pragma unroll
        for (int it = 0; it < 2; it++) {
            float4 w;
            w.x = __uint_as_float(f2tf(rB[it].x));
            w.y = __uint_as_float(f2tf(rB[it].y));
            w.z = __uint_as_float(f2tf(rB[it].z));
            w.w = __uint_as_float(f2tf(rB[it].w));
            *(float4*)&Bs[s][brow + it * 8][bcol] = w;
        }
    };

    fetch(0);
    commit(0);
    __syncthreads();

    int cur = 0;
    for (int k0 = 0; k0 < K; k0 += BKT, cur ^= 1) {
        const bool hasNext = (k0 + BKT) < K;
        if (hasNext) fetch(k0 + BKT);

#pragma unroll
        for (int kk = 0; kk < BKT; kk += 8) {
            unsigned af[4][4], bf[4][2];
#pragma unroll
            for (int i = 0; i < 4; i++) {
                int m0 = wm + 16 * i + qr;
                af[i][0] = __float_as_uint(As[cur][kk + qc][m0]);
                af[i][1] = __float_as_uint(As[cur][kk + qc][m0 + 8]);
                af[i][2] = __float_as_uint(As[cur][kk + qc + 4][m0]);
                af[i][3] = __float_as_uint(As[cur][kk + qc + 4][m0 + 8]);
            }
#pragma unroll
            for (int j = 0; j < 4; j++) {
                int n0 = wn + 8 * j + qr;
                bf[j][0] = __float_as_uint(Bs[cur][kk + qc][n0]);
                bf[j][1] = __float_as_uint(Bs[cur][kk + qc + 4][n0]);
            }
#pragma unroll
            for (int i = 0; i < 4; i++)
#pragma unroll
                for (int j = 0; j < 4; j++) {
                    asm volatile(
                        "mma.sync.aligned.m16n8k8.row.col.f32.tf32.tf32.f32 "
                        "{%0,%1,%2,%3}, {%4,%5,%6,%7}, {%8,%9}, {%0,%1,%2,%3};"
                        : "+f"(acc[i][j][0]), "+f"(acc[i][j][1]),
                          "+f"(acc[i][j][2]), "+f"(acc[i][j][3])
                        : "r"(af[i][0]), "r"(af[i][1]), "r"(af[i][2]), "r"(af[i][3]),
                          "r"(bf[j][0]), "r"(bf[j][1]));
                }
        }

        if (hasNext) commit(cur ^ 1);
        __syncthreads();
    }

    // ---- epilogue: bias add into acc, store, fused BN stats ----
#pragma unroll
    for (int j = 0; j < 4; j++) {
        int c = col0 + wn + 8 * j + 2 * qc;
        float bx = bias[c], by = bias[c + 1];
#pragma unroll
        for (int i = 0; i < 4; i++) {
            acc[i][j][0] += bx; acc[i][j][1] += by;
            acc[i][j][2] += bx; acc[i][j][3] += by;
        }
    }
#pragma unroll
    for (int i = 0; i < 4; i++) {
        int r = row0 + wm + 16 * i + qr;
#pragma unroll
        for (int j = 0; j < 4; j++) {
            int c = col0 + wn + 8 * j + 2 * qc;
            if (r < M)
                *(float2*)(C + (size_t)r * N + c) = make_float2(acc[i][j][0], acc[i][j][1]);
            if (r + 8 < M)
                *(float2*)(C + (size_t)(r + 8) * N + c) = make_float2(acc[i][j][2], acc[i][j][3]);
        }
    }
    // per-column partial sums over this CTA's rows, reduce across qr lanes, atomics
#pragma unroll
    for (int j = 0; j < 4; j++) {
        float s0 = 0.f, q0 = 0.f, s1 = 0.f, q1 = 0.f;
#pragma unroll
        for (int i = 0; i < 4; i++) {
            int r = row0 + wm + 16 * i + qr;
            if (r < M) {
                s0 += acc[i][j][0]; q0 += acc[i][j][0] * acc[i][j][0];
                s1 += acc[i][j][1]; q1 += acc[i][j][1] * acc[i][j][1];
            }
            if (r + 8 < M) {
                s0 += acc[i][j][2]; q0 += acc[i][j][2] * acc[i][j][2];
                s1 += acc[i][j][3]; q1 += acc[i][j][3] * acc[i][j][3];
            }
        }
#pragma unroll
        for (int off = 4; off < 32; off <<= 1) {
            s0 += __shfl_xor_sync(0xffffffff, s0, off);
            q0 += __shfl_xor_sync(0xffffffff, q0, off);
            s1 += __shfl_xor_sync(0xffffffff, s1, off);
            q1 += __shfl_xor_sync(0xffffffff, q1, off);
        }
        if (qr == 0) {
            int c = col0 + wn + 8 * j + 2 * qc;
            atomicAdd(&g_sums[soff + c], s0);
            atomicAdd(&g_ssqs[soff + c], q0);
            atomicAdd(&g_sums[soff + c + 1], s1);
            atomicAdd(&g_ssqs[soff + c + 1], q1);
        }
    }
}

// ---------------- BN apply (+ optional relu) ----------------
__global__ void k_bn_apply(int xid, const float* __restrict__ gamma,
                           const float* __restrict__ beta, int n, int F, int relu, int soff) {
    float* x = buf(xid);
    int idx = blockIdx.x * blockDim.x + threadIdx.x;
    if (idx >= n * F) return;
    int f = idx % F;
    float inv_n = 1.0f / (float)n;
    float mu = g_sums[soff + f] * inv_n;
    float var = g_ssqs[soff + f] * inv_n - mu * mu;
    float v = (x[idx] - mu) * rsqrtf(var + EPS) * gamma[f] + beta[f];
    if (relu) v = fmaxf(v, 0.0f);
    x[idx] = v;
}

// ---------------- propagation (CSR by dst, atomic-free) ----------------
__global__ void k_prop(int hid, int outid, int F) {
    const float* h = buf(hid);
    float* out = buf(outid);
    int node = blockIdx.x;
    int t = threadIdx.x;
    int beg = g_rowptr[node];
    int end = g_rowptr[node + 1];
    float4 acc = make_float4(0.f, 0.f, 0.f, 0.f);
    for (int e = beg; e < end; e++) {
        int s = g_csrc[e];
        float w = g_cw[e];
        float4 v = *(const float4*)(h + (size_t)s * F + t * 4);
        acc.x += w * v.x; acc.y += w * v.y; acc.z += w * v.z; acc.w += w * v.w;
    }
    *(float4*)(out + (size_t)node * F + t * 4) = acc;
}

__global__ void k_prop_cheb(int hid, int subid, int outid, int F) {
    const float* h = buf(hid);
    const float* sub = buf(subid);
    float* out = buf(outid);
    int node = blockIdx.x;
    int t = threadIdx.x;
    int beg = g_rowptr[node];
    int end = g_rowptr[node + 1];
    float4 acc = make_float4(0.f, 0.f, 0.f, 0.f);
    for (int e = beg; e < end; e++) {
        int s = g_csrc[e];
        float w = g_cw[e];
        float4 v = *(const float4*)(h + (size_t)s * F + t * 4);
        acc.x += w * v.x; acc.y += w * v.y; acc.z += w * v.z; acc.w += w * v.w;
    }
    float4 sv = *(const float4*)(sub + (size_t)node * F + t * 4);
    float4 r;
    r.x = 2.0f * acc.x - sv.x;
    r.y = 2.0f * acc.y - sv.y;
    r.z = 2.0f * acc.z - sv.z;
    r.w = 2.0f * acc.w - sv.w;
    *(float4*)(out + (size_t)node * F + t * 4) = r;
}

// ---------------- fc (128 -> 6) + log_softmax ----------------
__global__ void k_fc(const float* __restrict__ W,
                     const float* __restrict__ bias, float* __restrict__ out, int n) {
    const float* h = g_y3;
    int gtid = blockIdx.x * blockDim.x + threadIdx.x;
    int node = gtid >> 5;
    int lane = gtid & 31;
    if (node >= n) return;
    float hv[4];
#pragma unroll
    for (int k = 0; k < 4; k++) hv[k] = h[(size_t)node * 128 + lane + 32 * k];
    float logit[6];
#pragma unroll
    for (int j = 0; j < 6; j++) {
        float s = 0.0f;
#pragma unroll
        for (int k = 0; k < 4; k++) s += hv[k] * W[(lane + 32 * k) * 6 + j];
#pragma unroll
        for (int o = 16; o > 0; o >>= 1) s += __shfl_xor_sync(0xffffffff, s, o);
        logit[j] = s + bias[j];
    }
    if (lane == 0) {
        float mx = logit[0];
#pragma unroll
        for (int j = 1; j < 6; j++) mx = fmaxf(mx, logit[j]);
        float se = 0.0f;
#pragma unroll
        for (int j = 0; j < 6; j++) se += expf(logit[j] - mx);
        float lse = mx + logf(se);
#pragma unroll
        for (int j = 0; j < 6; j++) out[(size_t)node * 6 + j] = logit[j] - lse;
    }
}

// ---------------- launch ----------------
extern "C" void kernel_launch(void* const* d_in, const int* in_sizes, int n_in,
                              void* d_out, int out_size) {
    const float* x    = (const float*)d_in[0];
    const int*   ei   = (const int*)d_in[1];
    const float* ea   = (const float*)d_in[2];
    const float* W1_0 = (const float*)d_in[3];
    const float* b1   = (const float*)d_in[4];
    const float* g1   = (const float*)d_in[5];
    const float* be1  = (const float*)d_in[6];
    const float* W2_0 = (const float*)d_in[7];
    const float* W2_1 = (const float*)d_in[8];
    const float* b2   = (const float*)d_in[9];
    const float* g2   = (const float*)d_in[10];
    const float* be2  = (const float*)d_in[11];
    const float* W3_0 = (const float*)d_in[12];
    const float* W3_1 = (const float*)d_in[13];
    const float* W3_2 = (const float*)d_in[14];
    const float* b3   = (const float*)d_in[15];
    const float* g3   = (const float*)d_in[16];
    const float* be3  = (const float*)d_in[17];
    const float* fcW  = (const float*)d_in[18];
    const float* fcb  = (const float*)d_in[19];
    float* out = (float*)d_out;

    // ---- graph normalization + CSR build ----
    k_init_graph<<<CEILDIV(NN, 256), 256>>>();
    k_deg<<<CEILDIV(EE, 256), 256>>>(ei, ea);
    k_dis<<<CEILDIV(NN, 256), 256>>>();
    k_norm<<<CEILDIV(EE, 256), 256>>>(ei, ea);
    k_scan<<<1, 1024>>>();
    k_fill<<<CEILDIV(EE, 256), 256>>>(ei);

    // ---- layer 1: y1 = x @ W1_0 + b1 (stats fused) ; BN-apply+relu ----
    gemm_tf32<<<dim3(512 / BN, CEILDIV(NN, BM)), 256>>>(
        x, 0, 0, 0, W1_0, nullptr, nullptr, b1, 1, NN, 512, 768, 1, 0);
    k_bn_apply<<<CEILDIV(NN * 512, 256), 256>>>(1, g1, be1, NN, 512, 1, 0);

    // ---- layer 2: y2 = [h1 | prop(h1)] @ [W2_0 ; W2_1] + b2 (K=1024) ----
    k_prop<<<NN, 128>>>(1, 2, 512);
    gemm_tf32<<<dim3(256 / BN, CEILDIV(NN, BM)), 256>>>(
        nullptr, 1, 2, 0, W2_0, W2_1, nullptr, b2, 3, NN, 256, 512, 2, 512);
    k_bn_apply<<<CEILDIV(NN * 256, 256), 256>>>(3, g2, be2, NN, 256, 1, 512);

    // ---- layer 3: y3 = [h2 | Tx1 | Tx2] @ [W3_0;W3_1;W3_2] + b3 (K=768) ----
    k_prop<<<NN, 64>>>(3, 4, 256);
    k_prop_cheb<<<NN, 64>>>(4, 3, 5, 256);
    gemm_tf32<<<dim3(128 / BN, CEILDIV(NN, BM)), 256>>>(
        nullptr, 3, 4, 5, W3_0, W3_1, W3_2, b3, 6, NN, 128, 256, 3, 768);
    k_bn_apply<<<CEILDIV(NN * 128, 256), 256>>>(6, g3, be3, NN, 128, 0, 768);

    // ---- fc + log_softmax ----
    k_fc<<<CEILDIV(NN * 32, 256), 256>>>(fcW, fcb, out, NN);
}

// round 6
// speedup vs baseline: 2.2389x; 1.0746x over previous
#include <cuda_runtime.h>

#define NN 10000
#define EE 160000
#define EPS 1e-5f
#define ELLW 64
#define CEILDIV(a,b) (((a)+(b)-1)/(b))

// ---------------- scratch (static device globals; no allocation) ----------------
__device__ __align__(16) float g_deg[NN];
__device__ __align__(16) int   g_cnt[NN];          // ELL cursors / degrees
__device__ __align__(16) int   g_ell_src[NN * ELLW];
__device__ __align__(16) float g_ell_w[NN * ELLW];
__device__ __align__(16) float g_y1[NN * 512];     // h1
__device__ __align__(16) float g_t1[NN * 512];     // prop(h1)
__device__ __align__(16) float g_y2[NN * 256];     // h2
__device__ __align__(16) float g_p2[NN * 256];     // Tx1
__device__ __align__(16) float g_tx2[NN * 256];    // Tx2
__device__ __align__(16) float g_y3[NN * 128];     // h3
__device__ __align__(16) float g_sums[896];        // L1 @0, L2 @512, L3 @768
__device__ __align__(16) float g_ssqs[896];

__device__ __forceinline__ float* buf(int id) {
    switch (id) {
        case 1: return g_y1;
        case 2: return g_t1;
        case 3: return g_y2;
        case 4: return g_p2;
        case 5: return g_tx2;
        case 6: return g_y3;
    }
    return nullptr;
}

// ---------------- graph build (ELL by dst) ----------------
__global__ void k_init_graph() {
    int i = blockIdx.x * blockDim.x + threadIdx.x;
    if (i < NN) { g_deg[i] = 0.0f; g_cnt[i] = 0; }
    if (i < 896) { g_sums[i] = 0.0f; g_ssqs[i] = 0.0f; }
}
__global__ void k_deg(const int* __restrict__ ei, const float* __restrict__ ea) {
    int e = blockIdx.x * blockDim.x + threadIdx.x;
    if (e >= EE) return;
    atomicAdd(&g_deg[ei[e]], ea[e]);
}
__global__ void k_dis() {
    int i = blockIdx.x * blockDim.x + threadIdx.x;
    if (i >= NN) return;
    float d = g_deg[i];
    g_deg[i] = (d > 0.0f) ? rsqrtf(d) : 0.0f;
}
// normalize + push into ELL rows (atomic cursor)
__global__ void k_norm_push(const int* __restrict__ ei, const float* __restrict__ ea) {
    int e = blockIdx.x * blockDim.x + threadIdx.x;
    if (e >= EE) return;
    int s = ei[e];
    int d = ei[EE + e];
    float w = -g_deg[s] * ea[e] * g_deg[d];
    int pos = atomicAdd(&g_cnt[d], 1);
    g_ell_src[d * ELLW + pos] = s;
    g_ell_w[d * ELLW + pos] = w;
}

// ---------------- tf32 tensor-core GEMM, software-pipelined, fused BN stats ----------------
#define BN 128
#define BKT 16
#define SPAD 136

__device__ __forceinline__ unsigned f2tf(float x) {
    unsigned u;
    asm("cvt.rna.tf32.f32 %0, %1;" : "=r"(u) : "f"(x));
    return u;
}

template<int BM>
__global__ __launch_bounds__(256) void gemm_tf32(
    const float* __restrict__ Aext, int aid0, int aid1, int aid2,
    const float* __restrict__ B0, const float* __restrict__ B1, const float* __restrict__ B2,
    const float* __restrict__ bias, int Cid,
    int M, int N, int Kseg, int segs, int soff)
{
    constexpr int MI = BM / 32;          // m-subtiles per warp (4 for BM=128, 2 for BM=64)
    constexpr int AV = BM / 64;          // float4 A-loads per thread (2 or 1)
    __shared__ float As[2][BKT][SPAD];
    __shared__ float Bs[2][BKT][SPAD];

    const float* Ap[3];
    Ap[0] = Aext ? Aext : buf(aid0);
    Ap[1] = buf(aid1);
    Ap[2] = buf(aid2);
    const float* Bp[3] = {B0, B1, B2};
    float* C = buf(Cid);

    const int tid = threadIdx.x;
    const int lane = tid & 31;
    const int warp = tid >> 5;
    const int qr = lane >> 2;
    const int qc = lane & 3;
    const int wm = (warp & 1) * (BM / 2);
    const int wn = (warp >> 1) * 32;

    const int row0 = blockIdx.y * BM;
    const int col0 = blockIdx.x * BN;

    // A loader mapping: BM=128 -> row=tid/2, k=(tid&1)*8, 2x float4
    //                   BM=64  -> row=tid/4, k=(tid&3)*4, 1x float4
    const int arow = (BM == 128) ? (tid >> 1) : (tid >> 2);
    const int ak   = (BM == 128) ? ((tid & 1) << 3) : ((tid & 3) << 2);
    const bool avalid = (row0 + arow) < M;
    const int brow = tid >> 5;
    const int bcol = (tid & 31) << 2;

    float acc[MI][4][4];
#pragma unroll
    for (int i = 0; i < MI; i++)
#pragma unroll
        for (int j = 0; j < 4; j++)
#pragma unroll
            for (int e = 0; e < 4; e++) acc[i][j][e] = 0.0f;

    const int K = Kseg * segs;

    float4 rA[AV], rB[2];
    auto fetch = [&](int k0) {
        const int seg = k0 / Kseg;
        const int kloc = k0 - seg * Kseg;
        const float* A = Ap[seg];
        const float* B = Bp[seg];
        const float* Arow = A + (size_t)(row0 + arow) * Kseg + kloc + ak;
#pragma unroll
        for (int it = 0; it < AV; it++) {
            rA[it] = make_float4(0.f, 0.f, 0.f, 0.f);
            if (avalid) rA[it] = *(const float4*)(Arow + it * 4);
        }
#pragma unroll
        for (int it = 0; it < 2; it++) {
            rB[it] = *(const float4*)(B + (size_t)(kloc + brow + it * 8) * N + col0 + bcol);
        }
    };
    auto commit = [&](int s) {
#pragma unroll
        for (int it = 0; it < AV; it++) {
            int kb = ak + it * 4;
            As[s][kb + 0][arow] = __uint_as_float(f2tf(rA[it].x));
            As[s][kb + 1][arow] = __uint_as_float(f2tf(rA[it].y));
            As[s][kb + 2][arow] = __uint_as_float(f2tf(rA[it].z));
            As[s][kb + 3][arow] = __uint_as_float(f2tf(rA[it].w));
        }
#pragma unroll
        for (int it = 0; it < 2; it++) {
            float4 w;
            w.x = __uint_as_float(f2tf(rB[it].x));
            w.y = __uint_as_float(f2tf(rB[it].y));
            w.z = __uint_as_float(f2tf(rB[it].z));
            w.w = __uint_as_float(f2tf(rB[it].w));
            *(float4*)&Bs[s][brow + it * 8][bcol] = w;
        }
    };

    fetch(0);
    commit(0);
    __syncthreads();

    int cur = 0;
    for (int k0 = 0; k0 < K; k0 += BKT, cur ^= 1) {
        const bool hasNext = (k0 + BKT) < K;
        if (hasNext) fetch(k0 + BKT);

#pragma unroll
        for (int kk = 0; kk < BKT; kk += 8) {
            unsigned af[MI][4], bf[4][2];
#pragma unroll
            for (int i = 0; i < MI; i++) {
                int m0 = wm + 16 * i + qr;
                af[i][0] = __float_as_uint(As[cur][kk + qc][m0]);
                af[i][1] = __float_as_uint(As[cur][kk + qc][m0 + 8]);
                af[i][2] = __float_as_uint(As[cur][kk + qc + 4][m0]);
                af[i][3] = __float_as_uint(As[cur][kk + qc + 4][m0 + 8]);
            }
#pragma unroll
            for (int j = 0; j < 4; j++) {
                int n0 = wn + 8 * j + qr;
                bf[j][0] = __float_as_uint(Bs[cur][kk + qc][n0]);
                bf[j][1] = __float_as_uint(Bs[cur][kk + qc + 4][n0]);
            }
#pragma unroll
            for (int i = 0; i < MI; i++)
#pragma unroll
                for (int j = 0; j < 4; j++) {
                    asm volatile(
                        "mma.sync.aligned.m16n8k8.row.col.f32.tf32.tf32.f32 "
                        "{%0,%1,%2,%3}, {%4,%5,%6,%7}, {%8,%9}, {%0,%1,%2,%3};"
                        : "+f"(acc[i][j][0]), "+f"(acc[i][j][1]),
                          "+f"(acc[i][j][2]), "+f"(acc[i][j][3])
                        : "r"(af[i][0]), "r"(af[i][1]), "r"(af[i][2]), "r"(af[i][3]),
                          "r"(bf[j][0]), "r"(bf[j][1]));
                }
        }

        if (hasNext) commit(cur ^ 1);
        __syncthreads();
    }

    // ---- epilogue: bias add, store, fused BN stats ----
#pragma unroll
    for (int j = 0; j < 4; j++) {
        int c = col0 + wn + 8 * j + 2 * qc;
        float bx = bias[c], by = bias[c + 1];
#pragma unroll
        for (int i = 0; i < MI; i++) {
            acc[i][j][0] += bx; acc[i][j][1] += by;
            acc[i][j][2] += bx; acc[i][j][3] += by;
        }
    }
#pragma unroll
    for (int i = 0; i < MI; i++) {
        int r = row0 + wm + 16 * i + qr;
#pragma unroll
        for (int j = 0; j < 4; j++) {
            int c = col0 + wn + 8 * j + 2 * qc;
            if (r < M)
                *(float2*)(C + (size_t)r * N + c) = make_float2(acc[i][j][0], acc[i][j][1]);
            if (r + 8 < M)
                *(float2*)(C + (size_t)(r + 8) * N + c) = make_float2(acc[i][j][2], acc[i][j][3]);
        }
    }
#pragma unroll
    for (int j = 0; j < 4; j++) {
        float s0 = 0.f, q0 = 0.f, s1 = 0.f, q1 = 0.f;
#pragma unroll
        for (int i = 0; i < MI; i++) {
            int r = row0 + wm + 16 * i + qr;
            if (r < M) {
                s0 += acc[i][j][0]; q0 += acc[i][j][0] * acc[i][j][0];
                s1 += acc[i][j][1]; q1 += acc[i][j][1] * acc[i][j][1];
            }
            if (r + 8 < M) {
                s0 += acc[i][j][2]; q0 += acc[i][j][2] * acc[i][j][2];
                s1 += acc[i][j][3]; q1 += acc[i][j][3] * acc[i][j][3];
            }
        }
#pragma unroll
        for (int off = 4; off < 32; off <<= 1) {
            s0 += __shfl_xor_sync(0xffffffff, s0, off);
            q0 += __shfl_xor_sync(0xffffffff, q0, off);
            s1 += __shfl_xor_sync(0xffffffff, s1, off);
            q1 += __shfl_xor_sync(0xffffffff, q1, off);
        }
        if (qr == 0) {
            int c = col0 + wn + 8 * j + 2 * qc;
            atomicAdd(&g_sums[soff + c], s0);
            atomicAdd(&g_ssqs[soff + c], q0);
            atomicAdd(&g_sums[soff + c + 1], s1);
            atomicAdd(&g_ssqs[soff + c + 1], q1);
        }
    }
}

// ---------------- BN apply (+ optional relu), float4-vectorized ----------------
__global__ void k_bn_apply(int xid, const float* __restrict__ gamma,
                           const float* __restrict__ beta, int n, int F, int relu, int soff) {
    float* x = buf(xid);
    int idx = blockIdx.x * blockDim.x + threadIdx.x;   // float4 index
    if (idx >= n * F / 4) return;
    int f = (idx << 2) % F;
    float inv_n = 1.0f / (float)n;
    float4 v = *(float4*)(x + (size_t)idx * 4);
    float o[4];
#pragma unroll
    for (int c = 0; c < 4; c++) {
        float mu = g_sums[soff + f + c] * inv_n;
        float var = g_ssqs[soff + f + c] * inv_n - mu * mu;
        float val = (c == 0 ? v.x : c == 1 ? v.y : c == 2 ? v.z : v.w);
        float r = (val - mu) * rsqrtf(var + EPS) * gamma[f + c] + beta[f + c];
        o[c] = relu ? fmaxf(r, 0.0f) : r;
    }
    *(float4*)(x + (size_t)idx * 4) = make_float4(o[0], o[1], o[2], o[3]);
}

// ---------------- propagation (ELL by dst, atomic-free) ----------------
__global__ void k_prop(int hid, int outid, int F) {
    const float* h = buf(hid);
    float* out = buf(outid);
    int node = blockIdx.x;
    int t = threadIdx.x;
    int cnt = g_cnt[node];
    int base = node * ELLW;
    float4 acc = make_float4(0.f, 0.f, 0.f, 0.f);
    for (int e = 0; e < cnt; e++) {
        int s = g_ell_src[base + e];
        float w = g_ell_w[base + e];
        float4 v = *(const float4*)(h + (size_t)s * F + t * 4);
        acc.x += w * v.x; acc.y += w * v.y; acc.z += w * v.z; acc.w += w * v.w;
    }
    *(float4*)(out + (size_t)node * F + t * 4) = acc;
}

__global__ void k_prop_cheb(int hid, int subid, int outid, int F) {
    const float* h = buf(hid);
    const float* sub = buf(subid);
    float* out = buf(outid);
    int node = blockIdx.x;
    int t = threadIdx.x;
    int cnt = g_cnt[node];
    int base = node * ELLW;
    float4 acc = make_float4(0.f, 0.f, 0.f, 0.f);
    for (int e = 0; e < cnt; e++) {
        int s = g_ell_src[base + e];
        float w = g_ell_w[base + e];
        float4 v = *(const float4*)(h + (size_t)s * F + t * 4);
        acc.x += w * v.x; acc.y += w * v.y; acc.z += w * v.z; acc.w += w * v.w;
    }
    float4 sv = *(const float4*)(sub + (size_t)node * F + t * 4);
    float4 r;
    r.x = 2.0f * acc.x - sv.x;
    r.y = 2.0f * acc.y - sv.y;
    r.z = 2.0f * acc.z - sv.z;
    r.w = 2.0f * acc.w - sv.w;
    *(float4*)(out + (size_t)node * F + t * 4) = r;
}

// ---------------- fc (128 -> 6) + log_softmax ----------------
__global__ void k_fc(const float* __restrict__ W,
                     const float* __restrict__ bias, float* __restrict__ out, int n) {
    const float* h = g_y3;
    int gtid = blockIdx.x * blockDim.x + threadIdx.x;
    int node = gtid >> 5;
    int lane = gtid & 31;
    if (node >= n) return;
    float hv[4];
#pragma unroll
    for (int k = 0; k < 4; k++) hv[k] = h[(size_t)node * 128 + lane + 32 * k];
    float logit[6];
#pragma unroll
    for (int j = 0; j < 6; j++) {
        float s = 0.0f;
#pragma unroll
        for (int k = 0; k < 4; k++) s += hv[k] * W[(lane + 32 * k) * 6 + j];
#pragma unroll
        for (int o = 16; o > 0; o >>= 1) s += __shfl_xor_sync(0xffffffff, s, o);
        logit[j] = s + bias[j];
    }
    if (lane == 0) {
        float mx = logit[0];
#pragma unroll
        for (int j = 1; j < 6; j++) mx = fmaxf(mx, logit[j]);
        float se = 0.0f;
#pragma unroll
        for (int j = 0; j < 6; j++) se += expf(logit[j] - mx);
        float lse = mx + logf(se);
#pragma unroll
        for (int j = 0; j < 6; j++) out[(size_t)node * 6 + j] = logit[j] - lse;
    }
}

// ---------------- launch ----------------
extern "C" void kernel_launch(void* const* d_in, const int* in_sizes, int n_in,
                              void* d_out, int out_size) {
    const float* x    = (const float*)d_in[0];
    const int*   ei   = (const int*)d_in[1];
    const float* ea   = (const float*)d_in[2];
    const float* W1_0 = (const float*)d_in[3];
    const float* b1   = (const float*)d_in[4];
    const float* g1   = (const float*)d_in[5];
    const float* be1  = (const float*)d_in[6];
    const float* W2_0 = (const float*)d_in[7];
    const float* W2_1 = (const float*)d_in[8];
    const float* b2   = (const float*)d_in[9];
    const float* g2   = (const float*)d_in[10];
    const float* be2  = (const float*)d_in[11];
    const float* W3_0 = (const float*)d_in[12];
    const float* W3_1 = (const float*)d_in[13];
    const float* W3_2 = (const float*)d_in[14];
    const float* b3   = (const float*)d_in[15];
    const float* g3   = (const float*)d_in[16];
    const float* be3  = (const float*)d_in[17];
    const float* fcW  = (const float*)d_in[18];
    const float* fcb  = (const float*)d_in[19];
    float* out = (float*)d_out;

    // ---- graph normalization + ELL build (4 launches) ----
    k_init_graph<<<CEILDIV(NN, 256), 256>>>();
    k_deg<<<CEILDIV(EE, 256), 256>>>(ei, ea);
    k_dis<<<CEILDIV(NN, 256), 256>>>();
    k_norm_push<<<CEILDIV(EE, 256), 256>>>(ei, ea);

    // ---- layer 1: y1 = x @ W1_0 + b1 (stats fused) ; BN-apply+relu ----
    gemm_tf32<128><<<dim3(512 / BN, CEILDIV(NN, 128)), 256>>>(
        x, 0, 0, 0, W1_0, nullptr, nullptr, b1, 1, NN, 512, 768, 1, 0);
    k_bn_apply<<<CEILDIV(NN * 512 / 4, 256), 256>>>(1, g1, be1, NN, 512, 1, 0);

    // ---- layer 2: y2 = [h1 | prop(h1)] @ [W2_0 ; W2_1] + b2 (K=1024) ----
    k_prop<<<NN, 128>>>(1, 2, 512);
    gemm_tf32<128><<<dim3(256 / BN, CEILDIV(NN, 128)), 256>>>(
        nullptr, 1, 2, 0, W2_0, W2_1, nullptr, b2, 3, NN, 256, 512, 2, 512);
    k_bn_apply<<<CEILDIV(NN * 256 / 4, 256), 256>>>(3, g2, be2, NN, 256, 1, 512);

    // ---- layer 3: y3 = [h2 | Tx1 | Tx2] @ [W3_0;W3_1;W3_2] + b3 (K=768, BM=64) ----
    k_prop<<<NN, 64>>>(3, 4, 256);
    k_prop_cheb<<<NN, 64>>>(4, 3, 5, 256);
    gemm_tf32<64><<<dim3(128 / BN, CEILDIV(NN, 64)), 256>>>(
        nullptr, 3, 4, 5, W3_0, W3_1, W3_2, b3, 6, NN, 128, 256, 3, 768);
    k_bn_apply<<<CEILDIV(NN * 128 / 4, 256), 256>>>(6, g3, be3, NN, 128, 0, 768);

    // ---- fc + log_softmax ----
    k_fc<<<CEILDIV(NN * 32, 256), 256>>>(fcW, fcb, out, NN);
}

// round 7
// speedup vs baseline: 2.3051x; 1.0296x over previous
#include <cuda_runtime.h>

#define NN 10000
#define EE 160000
#define EPS 1e-5f
#define ELLW 64
#define CEILDIV(a,b) (((a)+(b)-1)/(b))

// ---------------- scratch (static device globals; no allocation) ----------------
__device__ __align__(16) float g_deg[NN];
__device__ __align__(16) int   g_cnt[NN];          // ELL cursors / degrees
__device__ __align__(16) int   g_ell_src[NN * ELLW];
__device__ __align__(16) float g_ell_w[NN * ELLW];
__device__ __align__(16) float g_y1[NN * 512];     // raw layer1 out
__device__ __align__(16) float g_t1[NN * 512];     // prop(bn1(y1))
__device__ __align__(16) float g_y2[NN * 256];     // raw layer2 out
__device__ __align__(16) float g_p2[NN * 256];     // Tx1 = prop(bn2(y2))
__device__ __align__(16) float g_tx2[NN * 256];    // Tx2
__device__ __align__(16) float g_y3[NN * 128];     // raw layer3 out
__device__ __align__(16) float g_sums[896];        // L1 @0, L2 @512, L3 @768
__device__ __align__(16) float g_ssqs[896];
__device__ __align__(16) float g_bnsc[896];        // BN scale  per column
__device__ __align__(16) float g_bnsh[896];        // BN shift  per column

__device__ __forceinline__ float* buf(int id) {
    switch (id) {
        case 1: return g_y1;
        case 2: return g_t1;
        case 3: return g_y2;
        case 4: return g_p2;
        case 5: return g_tx2;
        case 6: return g_y3;
    }
    return nullptr;
}

// ---------------- graph build (ELL by dst) ----------------
__global__ void k_init_graph() {
    int i = blockIdx.x * blockDim.x + threadIdx.x;
    if (i < NN) { g_deg[i] = 0.0f; g_cnt[i] = 0; }
    if (i < 896) { g_sums[i] = 0.0f; g_ssqs[i] = 0.0f; }
}
__global__ void k_deg(const int* __restrict__ ei, const float* __restrict__ ea) {
    int e = blockIdx.x * blockDim.x + threadIdx.x;
    if (e >= EE) return;
    atomicAdd(&g_deg[ei[e]], ea[e]);
}
// normalize (rsqrt on the fly) + push into ELL rows (atomic cursor)
__global__ void k_norm_push(const int* __restrict__ ei, const float* __restrict__ ea) {
    int e = blockIdx.x * blockDim.x + threadIdx.x;
    if (e >= EE) return;
    int s = ei[e];
    int d = ei[EE + e];
    float ds = g_deg[s], dd = g_deg[d];
    float is = (ds > 0.0f) ? rsqrtf(ds) : 0.0f;
    float id = (dd > 0.0f) ? rsqrtf(dd) : 0.0f;
    float w = -is * ea[e] * id;
    int pos = atomicAdd(&g_cnt[d], 1);
    g_ell_src[d * ELLW + pos] = s;
    g_ell_w[d * ELLW + pos] = w;
}

// ---------------- BN coefficients: sc = g*rsqrt(var+eps), sh = be - mu*sc ----------------
__global__ void k_bn_coef(const float* __restrict__ gamma, const float* __restrict__ beta,
                          int n, int F, int soff) {
    int f = threadIdx.x;
    if (f >= F) return;
    float inv_n = 1.0f / (float)n;
    float mu = g_sums[soff + f] * inv_n;
    float var = g_ssqs[soff + f] * inv_n - mu * mu;
    float sc = gamma[f] * rsqrtf(var + EPS);
    g_bnsc[soff + f] = sc;
    g_bnsh[soff + f] = beta[f] - mu * sc;
}

// ---------------- tf32 tensor-core GEMM, software-pipelined, fused BN stats ----------------
// A segments may have BN+ReLU applied on the fly (coefX >= 0 -> coef offset).
#define BN 128
#define BKT 16
#define SPAD 136

__device__ __forceinline__ unsigned f2tf(float x) {
    unsigned u;
    asm("cvt.rna.tf32.f32 %0, %1;" : "=r"(u) : "f"(x));
    return u;
}

template<int BM>
__global__ __launch_bounds__(256) void gemm_tf32(
    const float* __restrict__ Aext, int aid0, int aid1, int aid2,
    const float* __restrict__ B0, const float* __restrict__ B1, const float* __restrict__ B2,
    const float* __restrict__ bias, int Cid,
    int M, int N, int Kseg, int segs, int soff,
    int coff0, int coff1, int coff2)
{
    constexpr int MI = BM / 32;
    constexpr int AV = BM / 64;
    __shared__ float As[2][BKT][SPAD];
    __shared__ float Bs[2][BKT][SPAD];

    const float* Ap[3];
    Ap[0] = Aext ? Aext : buf(aid0);
    Ap[1] = buf(aid1);
    Ap[2] = buf(aid2);
    const float* Bp[3] = {B0, B1, B2};
    float* C = buf(Cid);

    const int tid = threadIdx.x;
    const int lane = tid & 31;
    const int warp = tid >> 5;
    const int qr = lane >> 2;
    const int qc = lane & 3;
    const int wm = (warp & 1) * (BM / 2);
    const int wn = (warp >> 1) * 32;

    const int row0 = blockIdx.y * BM;
    const int col0 = blockIdx.x * BN;

    const int arow = (BM == 128) ? (tid >> 1) : (tid >> 2);
    const int ak   = (BM == 128) ? ((tid & 1) << 3) : ((tid & 3) << 2);
    const bool avalid = (row0 + arow) < M;
    const int brow = tid >> 5;
    const int bcol = (tid & 31) << 2;

    float acc[MI][4][4];
#pragma unroll
    for (int i = 0; i < MI; i++)
#pragma unroll
        for (int j = 0; j < 4; j++)
#pragma unroll
            for (int e = 0; e < 4; e++) acc[i][j][e] = 0.0f;

    const int K = Kseg * segs;

    float4 rA[AV], rB[2];
    auto fetch = [&](int k0) {
        const int seg = k0 / Kseg;
        const int kloc = k0 - seg * Kseg;
        const int coff = (seg == 0) ? coff0 : (seg == 1) ? coff1 : coff2;
        const float* A = Ap[seg];
        const float* B = Bp[seg];
        const float* Arow = A + (size_t)(row0 + arow) * Kseg + kloc + ak;
#pragma unroll
        for (int it = 0; it < AV; it++) {
            rA[it] = make_float4(0.f, 0.f, 0.f, 0.f);
            if (avalid) rA[it] = *(const float4*)(Arow + it * 4);
        }
        if (coff >= 0) {
#pragma unroll
            for (int it = 0; it < AV; it++) {
                float4 sc = *(const float4*)(g_bnsc + coff + kloc + ak + it * 4);
                float4 sh = *(const float4*)(g_bnsh + coff + kloc + ak + it * 4);
                rA[it].x = fmaxf(fmaf(rA[it].x, sc.x, sh.x), 0.f);
                rA[it].y = fmaxf(fmaf(rA[it].y, sc.y, sh.y), 0.f);
                rA[it].z = fmaxf(fmaf(rA[it].z, sc.z, sh.z), 0.f);
                rA[it].w = fmaxf(fmaf(rA[it].w, sc.w, sh.w), 0.f);
            }
        }
#pragma unroll
        for (int it = 0; it < 2; it++) {
            rB[it] = *(const float4*)(B + (size_t)(kloc + brow + it * 8) * N + col0 + bcol);
        }
    };
    auto commit = [&](int s) {
#pragma unroll
        for (int it = 0; it < AV; it++) {
            int kb = ak + it * 4;
            As[s][kb + 0][arow] = __uint_as_float(f2tf(rA[it].x));
            As[s][kb + 1][arow] = __uint_as_float(f2tf(rA[it].y));
            As[s][kb + 2][arow] = __uint_as_float(f2tf(rA[it].z));
            As[s][kb + 3][arow] = __uint_as_float(f2tf(rA[it].w));
        }
#pragma unroll
        for (int it = 0; it < 2; it++) {
            float4 w;
            w.x = __uint_as_float(f2tf(rB[it].x));
            w.y = __uint_as_float(f2tf(rB[it].y));
            w.z = __uint_as_float(f2tf(rB[it].z));
            w.w = __uint_as_float(f2tf(rB[it].w));
            *(float4*)&Bs[s][brow + it * 8][bcol] = w;
        }
    };

    fetch(0);
    commit(0);
    __syncthreads();

    int cur = 0;
    for (int k0 = 0; k0 < K; k0 += BKT, cur ^= 1) {
        const bool hasNext = (k0 + BKT) < K;
        if (hasNext) fetch(k0 + BKT);

#pragma unroll
        for (int kk = 0; kk < BKT; kk += 8) {
            unsigned af[MI][4], bf[4][2];
#pragma unroll
            for (int i = 0; i < MI; i++) {
                int m0 = wm + 16 * i + qr;
                af[i][0] = __float_as_uint(As[cur][kk + qc][m0]);
                af[i][1] = __float_as_uint(As[cur][kk + qc][m0 + 8]);
                af[i][2] = __float_as_uint(As[cur][kk + qc + 4][m0]);
                af[i][3] = __float_as_uint(As[cur][kk + qc + 4][m0 + 8]);
            }
#pragma unroll
            for (int j = 0; j < 4; j++) {
                int n0 = wn + 8 * j + qr;
                bf[j][0] = __float_as_uint(Bs[cur][kk + qc][n0]);
                bf[j][1] = __float_as_uint(Bs[cur][kk + qc + 4][n0]);
            }
#pragma unroll
            for (int i = 0; i < MI; i++)
#pragma unroll
                for (int j = 0; j < 4; j++) {
                    asm volatile(
                        "mma.sync.aligned.m16n8k8.row.col.f32.tf32.tf32.f32 "
                        "{%0,%1,%2,%3}, {%4,%5,%6,%7}, {%8,%9}, {%0,%1,%2,%3};"
                        : "+f"(acc[i][j][0]), "+f"(acc[i][j][1]),
                          "+f"(acc[i][j][2]), "+f"(acc[i][j][3])
                        : "r"(af[i][0]), "r"(af[i][1]), "r"(af[i][2]), "r"(af[i][3]),
                          "r"(bf[j][0]), "r"(bf[j][1]));
                }
        }

        if (hasNext) commit(cur ^ 1);
        __syncthreads();
    }

    // ---- epilogue: bias add, store raw, fused BN stats ----
#pragma unroll
    for (int j = 0; j < 4; j++) {
        int c = col0 + wn + 8 * j + 2 * qc;
        float bx = bias[c], by = bias[c + 1];
#pragma unroll
        for (int i = 0; i < MI; i++) {
            acc[i][j][0] += bx; acc[i][j][1] += by;
            acc[i][j][2] += bx; acc[i][j][3] += by;
        }
    }
#pragma unroll
    for (int i = 0; i < MI; i++) {
        int r = row0 + wm + 16 * i + qr;
#pragma unroll
        for (int j = 0; j < 4; j++) {
            int c = col0 + wn + 8 * j + 2 * qc;
            if (r < M)
                *(float2*)(C + (size_t)r * N + c) = make_float2(acc[i][j][0], acc[i][j][1]);
            if (r + 8 < M)
                *(float2*)(C + (size_t)(r + 8) * N + c) = make_float2(acc[i][j][2], acc[i][j][3]);
        }
    }
#pragma unroll
    for (int j = 0; j < 4; j++) {
        float s0 = 0.f, q0 = 0.f, s1 = 0.f, q1 = 0.f;
#pragma unroll
        for (int i = 0; i < MI; i++) {
            int r = row0 + wm + 16 * i + qr;
            if (r < M) {
                s0 += acc[i][j][0]; q0 += acc[i][j][0] * acc[i][j][0];
                s1 += acc[i][j][1]; q1 += acc[i][j][1] * acc[i][j][1];
            }
            if (r + 8 < M) {
                s0 += acc[i][j][2]; q0 += acc[i][j][2] * acc[i][j][2];
                s1 += acc[i][j][3]; q1 += acc[i][j][3] * acc[i][j][3];
            }
        }
#pragma unroll
        for (int off = 4; off < 32; off <<= 1) {
            s0 += __shfl_xor_sync(0xffffffff, s0, off);
            q0 += __shfl_xor_sync(0xffffffff, q0, off);
            s1 += __shfl_xor_sync(0xffffffff, s1, off);
            q1 += __shfl_xor_sync(0xffffffff, q1, off);
        }
        if (qr == 0) {
            int c = col0 + wn + 8 * j + 2 * qc;
            atomicAdd(&g_sums[soff + c], s0);
            atomicAdd(&g_ssqs[soff + c], q0);
            atomicAdd(&g_sums[soff + c + 1], s1);
            atomicAdd(&g_ssqs[soff + c + 1], q1);
        }
    }
}

// ---------------- propagation (ELL by dst; BN+ReLU applied to gathered h) ----------------
__global__ void k_prop(int hid, int outid, int F, int coff) {
    const float* h = buf(hid);
    float* out = buf(outid);
    int node = blockIdx.x;
    int t = threadIdx.x;
    int cnt = g_cnt[node];
    int base = node * ELLW;
    float4 sc = make_float4(1.f, 1.f, 1.f, 1.f), sh = make_float4(0.f, 0.f, 0.f, 0.f);
    bool useC = coff >= 0;
    if (useC) {
        sc = *(const float4*)(g_bnsc + coff + t * 4);
        sh = *(const float4*)(g_bnsh + coff + t * 4);
    }
    float4 acc = make_float4(0.f, 0.f, 0.f, 0.f);
    for (int e = 0; e < cnt; e++) {
        int s = g_ell_src[base + e];
        float w = g_ell_w[base + e];
        float4 v = *(const float4*)(h + (size_t)s * F + t * 4);
        if (useC) {
            v.x = fmaxf(fmaf(v.x, sc.x, sh.x), 0.f);
            v.y = fmaxf(fmaf(v.y, sc.y, sh.y), 0.f);
            v.z = fmaxf(fmaf(v.z, sc.z, sh.z), 0.f);
            v.w = fmaxf(fmaf(v.w, sc.w, sh.w), 0.f);
        }
        acc.x += w * v.x; acc.y += w * v.y; acc.z += w * v.z; acc.w += w * v.w;
    }
    *(float4*)(out + (size_t)node * F + t * 4) = acc;
}

// Cheb step: out = 2*prop(h) - bnrelu(subRaw); h gathered raw (already propagated once)
__global__ void k_prop_cheb(int hid, int subid, int outid, int F, int subcoff) {
    const float* h = buf(hid);
    const float* sub = buf(subid);
    float* out = buf(outid);
    int node = blockIdx.x;
    int t = threadIdx.x;
    int cnt = g_cnt[node];
    int base = node * ELLW;
    float4 acc = make_float4(0.f, 0.f, 0.f, 0.f);
    for (int e = 0; e < cnt; e++) {
        int s = g_ell_src[base + e];
        float w = g_ell_w[base + e];
        float4 v = *(const float4*)(h + (size_t)s * F + t * 4);
        acc.x += w * v.x; acc.y += w * v.y; acc.z += w * v.z; acc.w += w * v.w;
    }
    float4 sc = *(const float4*)(g_bnsc + subcoff + t * 4);
    float4 sh = *(const float4*)(g_bnsh + subcoff + t * 4);
    float4 sv = *(const float4*)(sub + (size_t)node * F + t * 4);
    sv.x = fmaxf(fmaf(sv.x, sc.x, sh.x), 0.f);
    sv.y = fmaxf(fmaf(sv.y, sc.y, sh.y), 0.f);
    sv.z = fmaxf(fmaf(sv.z, sc.z, sh.z), 0.f);
    sv.w = fmaxf(fmaf(sv.w, sc.w, sh.w), 0.f);
    float4 r;
    r.x = 2.0f * acc.x - sv.x;
    r.y = 2.0f * acc.y - sv.y;
    r.z = 2.0f * acc.z - sv.z;
    r.w = 2.0f * acc.w - sv.w;
    *(float4*)(out + (size_t)node * F + t * 4) = r;
}

// ---------------- fc (bn3 applied on load; 128 -> 6) + log_softmax ----------------
__global__ void k_fc(const float* __restrict__ W,
                     const float* __restrict__ bias, float* __restrict__ out, int n) {
    const float* h = g_y3;
    int gtid = blockIdx.x * blockDim.x + threadIdx.x;
    int node = gtid >> 5;
    int lane = gtid & 31;
    if (node >= n) return;
    float hv[4];
#pragma unroll
    for (int k = 0; k < 4; k++) {
        int col = lane + 32 * k;
        float raw = h[(size_t)node * 128 + col];
        hv[k] = fmaf(raw, g_bnsc[768 + col], g_bnsh[768 + col]);
    }
    float logit[6];
#pragma unroll
    for (int j = 0; j < 6; j++) {
        float s = 0.0f;
#pragma unroll
        for (int k = 0; k < 4; k++) s += hv[k] * W[(lane + 32 * k) * 6 + j];
#pragma unroll
        for (int o = 16; o > 0; o >>= 1) s += __shfl_xor_sync(0xffffffff, s, o);
        logit[j] = s + bias[j];
    }
    if (lane == 0) {
        float mx = logit[0];
#pragma unroll
        for (int j = 1; j < 6; j++) mx = fmaxf(mx, logit[j]);
        float se = 0.0f;
#pragma unroll
        for (int j = 0; j < 6; j++) se += expf(logit[j] - mx);
        float lse = mx + logf(se);
#pragma unroll
        for (int j = 0; j < 6; j++) out[(size_t)node * 6 + j] = logit[j] - lse;
    }
}

// ---------------- launch ----------------
extern "C" void kernel_launch(void* const* d_in, const int* in_sizes, int n_in,
                              void* d_out, int out_size) {
    const float* x    = (const float*)d_in[0];
    const int*   ei   = (const int*)d_in[1];
    const float* ea   = (const float*)d_in[2];
    const float* W1_0 = (const float*)d_in[3];
    const float* b1   = (const float*)d_in[4];
    const float* g1   = (const float*)d_in[5];
    const float* be1  = (const float*)d_in[6];
    const float* W2_0 = (const float*)d_in[7];
    const float* W2_1 = (const float*)d_in[8];
    const float* b2   = (const float*)d_in[9];
    const float* g2   = (const float*)d_in[10];
    const float* be2  = (const float*)d_in[11];
    const float* W3_0 = (const float*)d_in[12];
    const float* W3_1 = (const float*)d_in[13];
    const float* W3_2 = (const float*)d_in[14];
    const float* b3   = (const float*)d_in[15];
    const float* g3   = (const float*)d_in[16];
    const float* be3  = (const float*)d_in[17];
    const float* fcW  = (const float*)d_in[18];
    const float* fcb  = (const float*)d_in[19];
    float* out = (float*)d_out;

    // ---- graph normalization + ELL build (3 launches) ----
    k_init_graph<<<CEILDIV(NN, 256), 256>>>();
    k_deg<<<CEILDIV(EE, 256), 256>>>(ei, ea);
    k_norm_push<<<CEILDIV(EE, 256), 256>>>(ei, ea);

    // ---- layer 1: y1 = x @ W1_0 + b1 (raw, stats fused) ----
    gemm_tf32<128><<<dim3(512 / BN, CEILDIV(NN, 128)), 256>>>(
        x, 0, 0, 0, W1_0, nullptr, nullptr, b1, 1, NN, 512, 768, 1, 0, -1, -1, -1);
    k_bn_coef<<<1, 512>>>(g1, be1, NN, 512, 0);

    // ---- layer 2: t1 = prop(bn1(y1)); y2 = [bn1(y1) | t1] @ [W2_0;W2_1] + b2 ----
    k_prop<<<NN, 128>>>(1, 2, 512, 0);
    gemm_tf32<128><<<dim3(256 / BN, CEILDIV(NN, 128)), 256>>>(
        nullptr, 1, 2, 0, W2_0, W2_1, nullptr, b2, 3, NN, 256, 512, 2, 512, 0, -1, -1);
    k_bn_coef<<<1, 256>>>(g2, be2, NN, 256, 512);

    // ---- layer 3: p2 = prop(bn2(y2)); tx2 = 2*prop(p2) - bn2(y2);
    //      y3 = [bn2(y2) | p2 | tx2] @ [W3_0;W3_1;W3_2] + b3 ----
    k_prop<<<NN, 64>>>(3, 4, 256, 512);
    k_prop_cheb<<<NN, 64>>>(4, 3, 5, 256, 512);
    gemm_tf32<64><<<dim3(128 / BN, CEILDIV(NN, 64)), 256>>>(
        nullptr, 3, 4, 5, W3_0, W3_1, W3_2, b3, 6, NN, 128, 256, 3, 768, 512, -1, -1);
    k_bn_coef<<<1, 128>>>(g3, be3, NN, 128, 768);

    // ---- fc (bn3 fused) + log_softmax ----
    k_fc<<<CEILDIV(NN * 32, 256), 256>>>(fcW, fcb, out, NN);
}

// round 8
// speedup vs baseline: 2.4854x; 1.0782x over previous
#include <cuda_runtime.h>

#define NN 10000
#define EE 160000
#define EPS 1e-5f
#define ELLW 64
#define CEILDIV(a,b) (((a)+(b)-1)/(b))

// ---------------- scratch (static device globals; no allocation) ----------------
__device__ __align__(16) float g_deg[NN];
__device__ __align__(16) int   g_cnt[NN];
__device__ __align__(16) int   g_ell_src[NN * ELLW];
__device__ __align__(16) float g_ell_w[NN * ELLW];
__device__ __align__(16) float g_y1[NN * 512];
__device__ __align__(16) float g_t1[NN * 512];
__device__ __align__(16) float g_y2[NN * 256];
__device__ __align__(16) float g_p2[NN * 256];
__device__ __align__(16) float g_tx2[NN * 256];
__device__ __align__(16) float g_y3[NN * 128];
__device__ __align__(16) float g_sums[896];
__device__ __align__(16) float g_ssqs[896];
__device__ __align__(16) float g_bnsc[896];
__device__ __align__(16) float g_bnsh[896];

__device__ __forceinline__ float* buf(int id) {
    switch (id) {
        case 1: return g_y1;
        case 2: return g_t1;
        case 3: return g_y2;
        case 4: return g_p2;
        case 5: return g_tx2;
        case 6: return g_y3;
    }
    return nullptr;
}

// ---------------- graph build (ELL by dst) ----------------
__global__ void k_init_graph() {
    int i = blockIdx.x * blockDim.x + threadIdx.x;
    if (i < NN) { g_deg[i] = 0.0f; g_cnt[i] = 0; }
    if (i < 896) { g_sums[i] = 0.0f; g_ssqs[i] = 0.0f; }
}
__global__ void k_deg(const int* __restrict__ ei, const float* __restrict__ ea) {
    int e = blockIdx.x * blockDim.x + threadIdx.x;
    if (e >= EE) return;
    atomicAdd(&g_deg[ei[e]], ea[e]);
}
__global__ void k_norm_push(const int* __restrict__ ei, const float* __restrict__ ea) {
    int e = blockIdx.x * blockDim.x + threadIdx.x;
    if (e >= EE) return;
    int s = ei[e];
    int d = ei[EE + e];
    float ds = g_deg[s], dd = g_deg[d];
    float is = (ds > 0.0f) ? rsqrtf(ds) : 0.0f;
    float id = (dd > 0.0f) ? rsqrtf(dd) : 0.0f;
    float w = -is * ea[e] * id;
    int pos = atomicAdd(&g_cnt[d], 1);
    g_ell_src[d * ELLW + pos] = s;
    g_ell_w[d * ELLW + pos] = w;
}

// ---------------- BN coefficients ----------------
__global__ void k_bn_coef(const float* __restrict__ gamma, const float* __restrict__ beta,
                          int n, int F, int soff) {
    int f = threadIdx.x;
    if (f >= F) return;
    float inv_n = 1.0f / (float)n;
    float mu = g_sums[soff + f] * inv_n;
    float var = g_ssqs[soff + f] * inv_n - mu * mu;
    float sc = gamma[f] * rsqrtf(var + EPS);
    g_bnsc[soff + f] = sc;
    g_bnsh[soff + f] = beta[f] - mu * sc;
}

// ---------------- tf32 GEMM: BM=64, BN=128, BKT=16, fragment-major A smem ----------------
#define BMT 64
#define BNT 128
#define BKT 16
#define NF 4                 // A fragments (16-row) per k-half
#define A_STAGE (2 * NF * 128)   // floats per stage (2 kh * 4 ms * 128)
#define BPAD 136

__device__ __forceinline__ unsigned f2tf(float x) {
    unsigned u;
    asm("cvt.rna.tf32.f32 %0, %1;" : "=r"(u) : "f"(x));
    return u;
}
__device__ __forceinline__ unsigned fui(float x) { return __float_as_uint(x); }

__global__ __launch_bounds__(256, 3) void gemm_tf32(
    const float* __restrict__ Aext, int aid0, int aid1, int aid2,
    const float* __restrict__ B0, const float* __restrict__ B1, const float* __restrict__ B2,
    const float* __restrict__ bias, int Cid,
    int M, int N, int Kseg, int segs, int soff,
    int coff0, int coff1, int coff2)
{
    __shared__ __align__(16) float As[2][A_STAGE];
    __shared__ __align__(16) float Bs[2][BKT][BPAD];

    const float* Ap[3];
    Ap[0] = Aext ? Aext : buf(aid0);
    Ap[1] = buf(aid1);
    Ap[2] = buf(aid2);
    const float* Bp[3] = {B0, B1, B2};
    float* C = buf(Cid);

    const int tid = threadIdx.x;
    const int lane = tid & 31;
    const int warp = tid >> 5;
    const int qr = lane >> 2;
    const int qc = lane & 3;
    const int wm = (warp & 1) * 32;
    const int ms0 = (warp & 1) * 2;
    const int wn = (warp >> 1) * 32;

    const int row0 = blockIdx.y * BMT;
    const int col0 = blockIdx.x * BNT;

    // A loader: each thread loads one float4: row=tid>>2, k=(tid&3)*4
    const int arow = tid >> 2;
    const int ak = (tid & 3) << 2;
    const bool avalid = (row0 + arow) < M;
    const int wr = arow & 15;                 // row within fragment
    const int wms = arow >> 4;                // fragment m index
    const int wkh = ak >> 3;                  // k-half
    const int wkb = (ak >> 2) & 1;            // k-quad within half
    const int xsw = ((wr >> 1) & 3) << 2;     // write xor (pre-shifted)
    const int awbase = (wkh * NF + wms) * 128 + ((wr & 7) << 4) + (wr >> 3) + (wkb << 1);

    // A fragment read base: pos = 4*qr + (qc ^ ((qr>>1)&3)); float4 at 4*pos
    const int rpos = (qr << 2) + (qc ^ ((qr >> 1) & 3));
    const int ardbase = ms0 * 128 + (rpos << 2);

    // B loader
    const int brow = tid >> 5;
    const int bcol = (tid & 31) << 2;

    float acc[2][4][4];
#pragma unroll
    for (int i = 0; i < 2; i++)
#pragma unroll
        for (int j = 0; j < 4; j++)
#pragma unroll
            for (int e = 0; e < 4; e++) acc[i][j][e] = 0.0f;

    const int K = Kseg * segs;

    float4 rA, rB[2];
    auto fetch = [&](int k0) {
        const int seg = k0 / Kseg;
        const int kloc = k0 - seg * Kseg;
        const int coff = (seg == 0) ? coff0 : (seg == 1) ? coff1 : coff2;
        const float* A = Ap[seg];
        const float* B = Bp[seg];
        rA = make_float4(0.f, 0.f, 0.f, 0.f);
        if (avalid) rA = *(const float4*)(A + (size_t)(row0 + arow) * Kseg + kloc + ak);
        if (coff >= 0) {
            float4 sc = *(const float4*)(g_bnsc + coff + kloc + ak);
            float4 sh = *(const float4*)(g_bnsh + coff + kloc + ak);
            rA.x = fmaxf(fmaf(rA.x, sc.x, sh.x), 0.f);
            rA.y = fmaxf(fmaf(rA.y, sc.y, sh.y), 0.f);
            rA.z = fmaxf(fmaf(rA.z, sc.z, sh.z), 0.f);
            rA.w = fmaxf(fmaf(rA.w, sc.w, sh.w), 0.f);
        }
#pragma unroll
        for (int it = 0; it < 2; it++)
            rB[it] = *(const float4*)(B + (size_t)(kloc + brow + it * 8) * N + col0 + bcol);
    };
    auto commit = [&](int s) {
        float* Aw = As[s];
        Aw[awbase + ((0 << 2) ^ xsw)] = __uint_as_float(f2tf(rA.x));
        Aw[awbase + ((1 << 2) ^ xsw)] = __uint_as_float(f2tf(rA.y));
        Aw[awbase + ((2 << 2) ^ xsw)] = __uint_as_float(f2tf(rA.z));
        Aw[awbase + ((3 << 2) ^ xsw)] = __uint_as_float(f2tf(rA.w));
#pragma unroll
        for (int it = 0; it < 2; it++) {
            float4 w;
            w.x = __uint_as_float(f2tf(rB[it].x));
            w.y = __uint_as_float(f2tf(rB[it].y));
            w.z = __uint_as_float(f2tf(rB[it].z));
            w.w = __uint_as_float(f2tf(rB[it].w));
            *(float4*)&Bs[s][brow + it * 8][bcol] = w;
        }
    };

    fetch(0);
    commit(0);
    __syncthreads();

    int cur = 0;
    for (int k0 = 0; k0 < K; k0 += BKT, cur ^= 1) {
        const bool hasNext = (k0 + BKT) < K;
        if (hasNext) fetch(k0 + BKT);

        const float* Ac = As[cur];
        const float* Bc = &Bs[cur][0][0];
#pragma unroll
        for (int kh = 0; kh < 2; kh++) {
            const float* Af = Ac + kh * (NF * 128) + ardbase;
            float4 fa0 = *(const float4*)(Af);
            float4 fa1 = *(const float4*)(Af + 128);
            const float* Bk0 = Bc + (kh * 8 + qc) * BPAD + wn + qr;
            const float* Bk1 = Bk0 + 4 * BPAD;
#pragma unroll
            for (int j = 0; j < 4; j++) {
                unsigned b0 = fui(Bk0[8 * j]);
                unsigned b1 = fui(Bk1[8 * j]);
                asm volatile(
                    "mma.sync.aligned.m16n8k8.row.col.f32.tf32.tf32.f32 "
                    "{%0,%1,%2,%3}, {%4,%5,%6,%7}, {%8,%9}, {%0,%1,%2,%3};"
                    : "+f"(acc[0][j][0]), "+f"(acc[0][j][1]),
                      "+f"(acc[0][j][2]), "+f"(acc[0][j][3])
                    : "r"(fui(fa0.x)), "r"(fui(fa0.y)), "r"(fui(fa0.z)), "r"(fui(fa0.w)),
                      "r"(b0), "r"(b1));
                asm volatile(
                    "mma.sync.aligned.m16n8k8.row.col.f32.tf32.tf32.f32 "
                    "{%0,%1,%2,%3}, {%4,%5,%6,%7}, {%8,%9}, {%0,%1,%2,%3};"
                    : "+f"(acc[1][j][0]), "+f"(acc[1][j][1]),
                      "+f"(acc[1][j][2]), "+f"(acc[1][j][3])
                    : "r"(fui(fa1.x)), "r"(fui(fa1.y)), "r"(fui(fa1.z)), "r"(fui(fa1.w)),
                      "r"(b0), "r"(b1));
            }
        }

        if (hasNext) commit(cur ^ 1);
        __syncthreads();
    }

    // ---- epilogue: bias add, store raw, fused BN stats ----
#pragma unroll
    for (int j = 0; j < 4; j++) {
        int c = col0 + wn + 8 * j + 2 * qc;
        float bx = bias[c], by = bias[c + 1];
#pragma unroll
        for (int i = 0; i < 2; i++) {
            acc[i][j][0] += bx; acc[i][j][1] += by;
            acc[i][j][2] += bx; acc[i][j][3] += by;
        }
    }
#pragma unroll
    for (int i = 0; i < 2; i++) {
        int r = row0 + wm + 16 * i + qr;
#pragma unroll
        for (int j = 0; j < 4; j++) {
            int c = col0 + wn + 8 * j + 2 * qc;
            if (r < M)
                *(float2*)(C + (size_t)r * N + c) = make_float2(acc[i][j][0], acc[i][j][1]);
            if (r + 8 < M)
                *(float2*)(C + (size_t)(r + 8) * N + c) = make_float2(acc[i][j][2], acc[i][j][3]);
        }
    }
#pragma unroll
    for (int j = 0; j < 4; j++) {
        float s0 = 0.f, q0 = 0.f, s1 = 0.f, q1 = 0.f;
#pragma unroll
        for (int i = 0; i < 2; i++) {
            int r = row0 + wm + 16 * i + qr;
            if (r < M) {
                s0 += acc[i][j][0]; q0 += acc[i][j][0] * acc[i][j][0];
                s1 += acc[i][j][1]; q1 += acc[i][j][1] * acc[i][j][1];
            }
            if (r + 8 < M) {
                s0 += acc[i][j][2]; q0 += acc[i][j][2] * acc[i][j][2];
                s1 += acc[i][j][3]; q1 += acc[i][j][3] * acc[i][j][3];
            }
        }
#pragma unroll
        for (int off = 4; off < 32; off <<= 1) {
            s0 += __shfl_xor_sync(0xffffffff, s0, off);
            q0 += __shfl_xor_sync(0xffffffff, q0, off);
            s1 += __shfl_xor_sync(0xffffffff, s1, off);
            q1 += __shfl_xor_sync(0xffffffff, q1, off);
        }
        if (qr == 0) {
            int c = col0 + wn + 8 * j + 2 * qc;
            atomicAdd(&g_sums[soff + c], s0);
            atomicAdd(&g_ssqs[soff + c], q0);
            atomicAdd(&g_sums[soff + c + 1], s1);
            atomicAdd(&g_ssqs[soff + c + 1], q1);
        }
    }
}

// ---------------- propagation (ELL by dst; BN+ReLU applied to gathered h) ----------------
__global__ void k_prop(int hid, int outid, int F, int coff) {
    const float* h = buf(hid);
    float* out = buf(outid);
    int node = blockIdx.x;
    int t = threadIdx.x;
    int cnt = g_cnt[node];
    int base = node * ELLW;
    float4 sc = make_float4(1.f, 1.f, 1.f, 1.f), sh = make_float4(0.f, 0.f, 0.f, 0.f);
    bool useC = coff >= 0;
    if (useC) {
        sc = *(const float4*)(g_bnsc + coff + t * 4);
        sh = *(const float4*)(g_bnsh + coff + t * 4);
    }
    float4 acc = make_float4(0.f, 0.f, 0.f, 0.f);
    for (int e = 0; e < cnt; e++) {
        int s = g_ell_src[base + e];
        float w = g_ell_w[base + e];
        float4 v = *(const float4*)(h + (size_t)s * F + t * 4);
        if (useC) {
            v.x = fmaxf(fmaf(v.x, sc.x, sh.x), 0.f);
            v.y = fmaxf(fmaf(v.y, sc.y, sh.y), 0.f);
            v.z = fmaxf(fmaf(v.z, sc.z, sh.z), 0.f);
            v.w = fmaxf(fmaf(v.w, sc.w, sh.w), 0.f);
        }
        acc.x += w * v.x; acc.y += w * v.y; acc.z += w * v.z; acc.w += w * v.w;
    }
    *(float4*)(out + (size_t)node * F + t * 4) = acc;
}

__global__ void k_prop_cheb(int hid, int subid, int outid, int F, int subcoff) {
    const float* h = buf(hid);
    const float* sub = buf(subid);
    float* out = buf(outid);
    int node = blockIdx.x;
    int t = threadIdx.x;
    int cnt = g_cnt[node];
    int base = node * ELLW;
    float4 acc = make_float4(0.f, 0.f, 0.f, 0.f);
    for (int e = 0; e < cnt; e++) {
        int s = g_ell_src[base + e];
        float w = g_ell_w[base + e];
        float4 v = *(const float4*)(h + (size_t)s * F + t * 4);
        acc.x += w * v.x; acc.y += w * v.y; acc.z += w * v.z; acc.w += w * v.w;
    }
    float4 sc = *(const float4*)(g_bnsc + subcoff + t * 4);
    float4 sh = *(const float4*)(g_bnsh + subcoff + t * 4);
    float4 sv = *(const float4*)(sub + (size_t)node * F + t * 4);
    sv.x = fmaxf(fmaf(sv.x, sc.x, sh.x), 0.f);
    sv.y = fmaxf(fmaf(sv.y, sc.y, sh.y), 0.f);
    sv.z = fmaxf(fmaf(sv.z, sc.z, sh.z), 0.f);
    sv.w = fmaxf(fmaf(sv.w, sc.w, sh.w), 0.f);
    float4 r;
    r.x = 2.0f * acc.x - sv.x;
    r.y = 2.0f * acc.y - sv.y;
    r.z = 2.0f * acc.z - sv.z;
    r.w = 2.0f * acc.w - sv.w;
    *(float4*)(out + (size_t)node * F + t * 4) = r;
}

// ---------------- fc (bn3 on load; 128 -> 6) + log_softmax ----------------
__global__ void k_fc(const float* __restrict__ W,
                     const float* __restrict__ bias, float* __restrict__ out, int n) {
    const float* h = g_y3;
    int gtid = blockIdx.x * blockDim.x + threadIdx.x;
    int node = gtid >> 5;
    int lane = gtid & 31;
    if (node >= n) return;
    float hv[4];
#pragma unroll
    for (int k = 0; k < 4; k++) {
        int col = lane + 32 * k;
        float raw = h[(size_t)node * 128 + col];
        hv[k] = fmaf(raw, g_bnsc[768 + col], g_bnsh[768 + col]);
    }
    float logit[6];
#pragma unroll
    for (int j = 0; j < 6; j++) {
        float s = 0.0f;
#pragma unroll
        for (int k = 0; k < 4; k++) s += hv[k] * W[(lane + 32 * k) * 6 + j];
#pragma unroll
        for (int o = 16; o > 0; o >>= 1) s += __shfl_xor_sync(0xffffffff, s, o);
        logit[j] = s + bias[j];
    }
    if (lane == 0) {
        float mx = logit[0];
#pragma unroll
        for (int j = 1; j < 6; j++) mx = fmaxf(mx, logit[j]);
        float se = 0.0f;
#pragma unroll
        for (int j = 0; j < 6; j++) se += expf(logit[j] - mx);
        float lse = mx + logf(se);
#pragma unroll
        for (int j = 0; j < 6; j++) out[(size_t)node * 6 + j] = logit[j] - lse;
    }
}

// ---------------- launch ----------------
extern "C" void kernel_launch(void* const* d_in, const int* in_sizes, int n_in,
                              void* d_out, int out_size) {
    const float* x    = (const float*)d_in[0];
    const int*   ei   = (const int*)d_in[1];
    const float* ea   = (const float*)d_in[2];
    const float* W1_0 = (const float*)d_in[3];
    const float* b1   = (const float*)d_in[4];
    const float* g1   = (const float*)d_in[5];
    const float* be1  = (const float*)d_in[6];
    const float* W2_0 = (const float*)d_in[7];
    const float* W2_1 = (const float*)d_in[8];
    const float* b2   = (const float*)d_in[9];
    const float* g2   = (const float*)d_in[10];
    const float* be2  = (const float*)d_in[11];
    const float* W3_0 = (const float*)d_in[12];
    const float* W3_1 = (const float*)d_in[13];
    const float* W3_2 = (const float*)d_in[14];
    const float* b3   = (const float*)d_in[15];
    const float* g3   = (const float*)d_in[16];
    const float* be3  = (const float*)d_in[17];
    const float* fcW  = (const float*)d_in[18];
    const float* fcb  = (const float*)d_in[19];
    float* out = (float*)d_out;

    // ---- graph normalization + ELL build ----
    k_init_graph<<<CEILDIV(NN, 256), 256>>>();
    k_deg<<<CEILDIV(EE, 256), 256>>>(ei, ea);
    k_norm_push<<<CEILDIV(EE, 256), 256>>>(ei, ea);

    const int GY = CEILDIV(NN, BMT);   // 157

    // ---- layer 1: y1 = x @ W1_0 + b1 (raw, stats fused) ----
    gemm_tf32<<<dim3(512 / BNT, GY), 256>>>(
        x, 0, 0, 0, W1_0, nullptr, nullptr, b1, 1, NN, 512, 768, 1, 0, -1, -1, -1);
    k_bn_coef<<<1, 512>>>(g1, be1, NN, 512, 0);

    // ---- layer 2 ----
    k_prop<<<NN, 128>>>(1, 2, 512, 0);
    gemm_tf32<<<dim3(256 / BNT, GY), 256>>>(
        nullptr, 1, 2, 0, W2_0, W2_1, nullptr, b2, 3, NN, 256, 512, 2, 512, 0, -1, -1);
    k_bn_coef<<<1, 256>>>(g2, be2, NN, 256, 512);

    // ---- layer 3 ----
    k_prop<<<NN, 64>>>(3, 4, 256, 512);
    k_prop_cheb<<<NN, 64>>>(4, 3, 5, 256, 512);
    gemm_tf32<<<dim3(128 / BNT, GY), 256>>>(
        nullptr, 3, 4, 5, W3_0, W3_1, W3_2, b3, 6, NN, 128, 256, 3, 768, 512, -1, -1);
    k_bn_coef<<<1, 128>>>(g3, be3, NN, 128, 768);

    // ---- fc (bn3 fused) + log_softmax ----
    k_fc<<<CEILDIV(NN * 32, 256), 256>>>(fcW, fcb, out, NN);
}